// round 1
// baseline (speedup 1.0000x reference)
#include <cuda_runtime.h>
#include <cuda_bf16.h>
#include <cstdint>

// ============================================================================
// AttentionWithRoPE — fp32 baseline with packed f32x2 FFMA (sm_100a)
//   B=2, N=2048, D=2048, H=16, Dh=128
//   1) Q = x@Wq, K = x@Wk, V = x@Wv          (sgemm_kernel, f32x2)
//   2) RoPE(+1/sqrt(Dh) scale on Q)          (rope_kernel)
//   3) flash attention, online softmax       (attn_kernel, f32x2)
//   4) out = att@Wo + bo                     (sgemm_kernel with bias)
// All fp32 end-to-end => rel_err ~1e-6.
// ============================================================================

#define BATCH   2
#define SEQ     2048
#define DMODEL  2048
#define HEADS   16
#define DH      128
#define ROWS    (BATCH * SEQ)          // 4096

// ---- scratch (static __device__, no allocations) ----
__device__ float g_q[ROWS * DMODEL];
__device__ float g_k[ROWS * DMODEL];
__device__ float g_v[ROWS * DMODEL];
__device__ float g_att[ROWS * DMODEL];

// ---- packed f32x2 helpers ----
__device__ __forceinline__ unsigned long long pack2(float lo, float hi) {
    unsigned long long d;
    asm("mov.b64 %0, {%1, %2};" : "=l"(d) : "f"(lo), "f"(hi));
    return d;
}
__device__ __forceinline__ void unpack2(unsigned long long v, float& lo, float& hi) {
    asm("mov.b64 {%0, %1}, %2;" : "=f"(lo), "=f"(hi) : "l"(v));
}
__device__ __forceinline__ unsigned long long ffma2(unsigned long long a,
                                                    unsigned long long b,
                                                    unsigned long long c) {
    unsigned long long d;
    asm("fma.rn.f32x2 %0, %1, %2, %3;" : "=l"(d) : "l"(a), "l"(b), "l"(c));
    return d;
}
__device__ __forceinline__ unsigned long long fmul2(unsigned long long a,
                                                    unsigned long long b) {
    unsigned long long d;
    asm("mul.rn.f32x2 %0, %1, %2;" : "=l"(d) : "l"(a), "l"(b));
    return d;
}

// ============================================================================
// SGEMM: C[M,N] = A[M,K] @ B[K,N] (+ bias).  BM=BN=128, BK=16, 256 threads,
// 8x8 per thread with packed f32x2 accumulators.  M,N,K multiples of 128/16.
// ============================================================================
__global__ __launch_bounds__(256, 2)
void sgemm_kernel(const float* __restrict__ A, const float* __restrict__ B,
                  float* __restrict__ C, int M, int N, int K,
                  const float* __restrict__ bias) {
    __shared__ float As[16][128];   // As[k][m]
    __shared__ float Bs[16][128];   // Bs[k][n]

    const int tid = threadIdx.x;
    const int tx = tid & 15;        // 0..15 -> N microtile
    const int ty = tid >> 4;        // 0..15 -> M microtile
    const int bx = blockIdx.x;      // N tile
    const int by = blockIdx.y;      // M tile

    unsigned long long acc[8][4];   // acc[i][j] = cols (tx*8+2j, tx*8+2j+1)
#pragma unroll
    for (int i = 0; i < 8; i++)
#pragma unroll
        for (int j = 0; j < 4; j++) acc[i][j] = 0ull;

    const int arow = tid >> 2;            // 0..63
    const int acol = (tid & 3) << 2;      // 0,4,8,12
    const int brow = tid >> 5;            // 0..7
    const int bcol = (tid & 31) << 2;     // 0..124

    const float* Ap = A + (size_t)(by * 128 + arow) * K + acol;
    const float* Bp = B + (size_t)brow * N + bx * 128 + bcol;

    for (int k0 = 0; k0 < K; k0 += 16) {
        float4 a0 = *(const float4*)(Ap + k0);
        float4 a1 = *(const float4*)(Ap + (size_t)64 * K + k0);
        float4 b0 = *(const float4*)(Bp + (size_t)k0 * N);
        float4 b1 = *(const float4*)(Bp + (size_t)(k0 + 8) * N);

        __syncthreads();   // previous tile's compute finished reading smem
        As[acol + 0][arow] = a0.x; As[acol + 1][arow] = a0.y;
        As[acol + 2][arow] = a0.z; As[acol + 3][arow] = a0.w;
        As[acol + 0][arow + 64] = a1.x; As[acol + 1][arow + 64] = a1.y;
        As[acol + 2][arow + 64] = a1.z; As[acol + 3][arow + 64] = a1.w;
        *(float4*)&Bs[brow][bcol]     = b0;
        *(float4*)&Bs[brow + 8][bcol] = b1;
        __syncthreads();

#pragma unroll
        for (int kk = 0; kk < 16; kk++) {
            float4 af0 = *(const float4*)&As[kk][ty * 8];
            float4 af1 = *(const float4*)&As[kk][ty * 8 + 4];
            const unsigned long long* bp =
                (const unsigned long long*)&Bs[kk][tx * 8];
            unsigned long long bb0 = bp[0], bb1 = bp[1], bb2 = bp[2], bb3 = bp[3];
            float a[8] = {af0.x, af0.y, af0.z, af0.w, af1.x, af1.y, af1.z, af1.w};
#pragma unroll
            for (int i = 0; i < 8; i++) {
                unsigned long long ad = pack2(a[i], a[i]);
                acc[i][0] = ffma2(ad, bb0, acc[i][0]);
                acc[i][1] = ffma2(ad, bb1, acc[i][1]);
                acc[i][2] = ffma2(ad, bb2, acc[i][2]);
                acc[i][3] = ffma2(ad, bb3, acc[i][3]);
            }
        }
    }

    const int crow0 = by * 128 + ty * 8;
    const int ccol0 = bx * 128 + tx * 8;
    float bv[8];
    if (bias) {
        float4 bb0 = *(const float4*)(bias + ccol0);
        float4 bb1 = *(const float4*)(bias + ccol0 + 4);
        bv[0]=bb0.x; bv[1]=bb0.y; bv[2]=bb0.z; bv[3]=bb0.w;
        bv[4]=bb1.x; bv[5]=bb1.y; bv[6]=bb1.z; bv[7]=bb1.w;
    } else {
#pragma unroll
        for (int j = 0; j < 8; j++) bv[j] = 0.0f;
    }
#pragma unroll
    for (int i = 0; i < 8; i++) {
        float c[8];
#pragma unroll
        for (int j = 0; j < 4; j++) unpack2(acc[i][j], c[2 * j], c[2 * j + 1]);
#pragma unroll
        for (int j = 0; j < 8; j++) c[j] += bv[j];
        float* Cp = C + (size_t)(crow0 + i) * N + ccol0;
        *(float4*)Cp       = make_float4(c[0], c[1], c[2], c[3]);
        *(float4*)(Cp + 4) = make_float4(c[4], c[5], c[6], c[7]);
    }
}

// ============================================================================
// RoPE (in-place on [B,N,H*Dh]; rope table [B,N,Dh] broadcast over heads)
// ============================================================================
__global__ __launch_bounds__(256)
void rope_kernel(float* __restrict__ X, const float* __restrict__ rope,
                 float scale) {
    int i = blockIdx.x * blockDim.x + threadIdx.x;   // pair index
    // total pairs = B*N*H*(Dh/2) = 4096*16*64
    int p  = i & 63;            // pair within head
    int h  = (i >> 6) & 15;     // head
    int bn = i >> 10;           // 0..4095
    float rr = rope[bn * DH + 2 * p];
    float ri = rope[bn * DH + 2 * p + 1];
    float* base = X + (size_t)bn * DMODEL + h * DH + 2 * p;
    float xr = base[0] * scale;
    float xi = base[1] * scale;
    base[0] = xr * rr - xi * ri;
    base[1] = xr * ri + xi * rr;
}

// ============================================================================
// Flash attention: per block one (b,h) and a 64-query tile; loop over 64-key
// tiles with online softmax.  256 threads = 16(tx: keys/dcols) x 16(ty: rows).
// Smem: Qs[64][129], KVs[64][129] (K then V reuse), Ps[64][65].
// ============================================================================
#define ATT_QS_ELEMS  (64 * 129)
#define ATT_PS_ELEMS  (64 * 65)
#define ATT_SMEM_BYTES ((2 * ATT_QS_ELEMS + ATT_PS_ELEMS) * 4)

__device__ __forceinline__ float redmax16(float v) {
    v = fmaxf(v, __shfl_xor_sync(0xffffffffu, v, 1, 16));
    v = fmaxf(v, __shfl_xor_sync(0xffffffffu, v, 2, 16));
    v = fmaxf(v, __shfl_xor_sync(0xffffffffu, v, 4, 16));
    v = fmaxf(v, __shfl_xor_sync(0xffffffffu, v, 8, 16));
    return v;
}
__device__ __forceinline__ float redsum16(float v) {
    v += __shfl_xor_sync(0xffffffffu, v, 1, 16);
    v += __shfl_xor_sync(0xffffffffu, v, 2, 16);
    v += __shfl_xor_sync(0xffffffffu, v, 4, 16);
    v += __shfl_xor_sync(0xffffffffu, v, 8, 16);
    return v;
}

// load 64 rows x 128 floats from gmem (row stride DMODEL) -> smem pitch 129
__device__ __forceinline__ void load_tile_64x128(float* dst, const float* src,
                                                 int tid) {
#pragma unroll
    for (int it = 0; it < 8; it++) {
        int idx = tid + it * 256;
        int r   = idx >> 5;
        int c4  = (idx & 31) << 2;
        float4 v4 = *(const float4*)(src + (size_t)r * DMODEL + c4);
        float* d = dst + r * 129 + c4;
        d[0] = v4.x; d[1] = v4.y; d[2] = v4.z; d[3] = v4.w;
    }
}

__global__ __launch_bounds__(256, 2)
void attn_kernel(const float* __restrict__ Q, const float* __restrict__ K,
                 const float* __restrict__ V, float* __restrict__ O) {
    extern __shared__ float sm[];
    float* Qs  = sm;                       // [64][129]
    float* KVs = sm + ATT_QS_ELEMS;        // [64][129]
    float* Ps  = sm + 2 * ATT_QS_ELEMS;    // [64][65]

    const int tid = threadIdx.x;
    const int tx = tid & 15;
    const int ty = tid >> 4;
    const int qt = blockIdx.x;             // query tile (32)
    const int bh = blockIdx.y;             // b*H + h (32)
    const int b  = bh >> 4;
    const int h  = bh & 15;

    const float* Qg = Q + ((size_t)b * SEQ + qt * 64) * DMODEL + h * DH;
    const float* Kg = K + ((size_t)b * SEQ) * DMODEL + h * DH;
    const float* Vg = V + ((size_t)b * SEQ) * DMODEL + h * DH;
    float*       Og = O + ((size_t)b * SEQ + qt * 64) * DMODEL + h * DH;

    load_tile_64x128(Qs, Qg, tid);

    const float sscale = 0.08838834764831845f;   // 1/sqrt(128)

    float m_i[4], l_i[4];
    unsigned long long Oacc[4][4];  // [row i][pair j]: cols (tx+32j, tx+32j+16)
#pragma unroll
    for (int i = 0; i < 4; i++) {
        m_i[i] = -1e30f;
        l_i[i] = 0.0f;
#pragma unroll
        for (int j = 0; j < 4; j++) Oacc[i][j] = 0ull;
    }

    int qb[4], kb[4];
#pragma unroll
    for (int i = 0; i < 4; i++) qb[i] = (4 * ty + i) * 129;
#pragma unroll
    for (int j = 0; j < 4; j++) kb[j] = (4 * tx + j) * 129;

    for (int kt = 0; kt < SEQ / 64; kt++) {
        __syncthreads();   // previous PV done reading KVs (and Qs visible)
        load_tile_64x128(KVs, Kg + (size_t)(kt * 64) * DMODEL, tid);
        __syncthreads();

        // ---- scores S = Q K^T (4x4 microtile, packed pairs over j) ----
        unsigned long long S2[4][2];
#pragma unroll
        for (int i = 0; i < 4; i++) { S2[i][0] = 0ull; S2[i][1] = 0ull; }
#pragma unroll 4
        for (int d = 0; d < DH; d++) {
            float b0 = KVs[kb[0] + d], b1 = KVs[kb[1] + d];
            float b2 = KVs[kb[2] + d], b3 = KVs[kb[3] + d];
            unsigned long long bp0 = pack2(b0, b1);
            unsigned long long bp1 = pack2(b2, b3);
#pragma unroll
            for (int i = 0; i < 4; i++) {
                float a = Qs[qb[i] + d];
                unsigned long long ad = pack2(a, a);
                S2[i][0] = ffma2(ad, bp0, S2[i][0]);
                S2[i][1] = ffma2(ad, bp1, S2[i][1]);
            }
        }

        // ---- online softmax ----
#pragma unroll
        for (int i = 0; i < 4; i++) {
            float s0, s1, s2, s3;
            unpack2(S2[i][0], s0, s1);
            unpack2(S2[i][1], s2, s3);
            s0 *= sscale; s1 *= sscale; s2 *= sscale; s3 *= sscale;
            float rm = fmaxf(fmaxf(s0, s1), fmaxf(s2, s3));
            rm = redmax16(rm);
            float mn = fmaxf(m_i[i], rm);
            float alpha = __expf(m_i[i] - mn);
            float p0 = __expf(s0 - mn);
            float p1 = __expf(s1 - mn);
            float p2 = __expf(s2 - mn);
            float p3 = __expf(s3 - mn);
            float rs = redsum16(p0 + p1 + p2 + p3);
            l_i[i] = l_i[i] * alpha + rs;
            m_i[i] = mn;
            float* prow = &Ps[(4 * ty + i) * 65 + 4 * tx];
            prow[0] = p0; prow[1] = p1; prow[2] = p2; prow[3] = p3;
            unsigned long long ad = pack2(alpha, alpha);
#pragma unroll
            for (int j = 0; j < 4; j++) Oacc[i][j] = fmul2(Oacc[i][j], ad);
        }

        __syncthreads();   // Ps written; all K reads done
        load_tile_64x128(KVs, Vg + (size_t)(kt * 64) * DMODEL, tid);
        __syncthreads();

        // ---- O += P @ V ----
#pragma unroll 2
        for (int kk = 0; kk < 64; kk++) {
            const float* vrow = &KVs[kk * 129 + tx];
            unsigned long long v0 = pack2(vrow[0],  vrow[16]);
            unsigned long long v1 = pack2(vrow[32], vrow[48]);
            unsigned long long v2 = pack2(vrow[64], vrow[80]);
            unsigned long long v3 = pack2(vrow[96], vrow[112]);
#pragma unroll
            for (int i = 0; i < 4; i++) {
                float p = Ps[(4 * ty + i) * 65 + kk];
                unsigned long long pd = pack2(p, p);
                Oacc[i][0] = ffma2(pd, v0, Oacc[i][0]);
                Oacc[i][1] = ffma2(pd, v1, Oacc[i][1]);
                Oacc[i][2] = ffma2(pd, v2, Oacc[i][2]);
                Oacc[i][3] = ffma2(pd, v3, Oacc[i][3]);
            }
        }
    }

    // ---- normalize + write ----
#pragma unroll
    for (int i = 0; i < 4; i++) {
        float inv = 1.0f / l_i[i];
        float* orow = Og + (size_t)(4 * ty + i) * DMODEL;
#pragma unroll
        for (int j = 0; j < 4; j++) {
            float lo, hi;
            unpack2(Oacc[i][j], lo, hi);
            orow[tx + 32 * j]      = lo * inv;
            orow[tx + 32 * j + 16] = hi * inv;
        }
    }
}

// ============================================================================
// host
// ============================================================================
extern "C" void kernel_launch(void* const* d_in, const int* in_sizes, int n_in,
                              void* d_out, int out_size) {
    const float* x   = (const float*)d_in[0];
    const float* qr  = (const float*)d_in[1];
    const float* kr  = (const float*)d_in[2];
    const float* Wq  = (const float*)d_in[3];
    const float* Wk  = (const float*)d_in[4];
    const float* Wv  = (const float*)d_in[5];
    const float* Wo  = (const float*)d_in[6];
    const float* bo  = (const float*)d_in[7];
    float* out = (float*)d_out;

    void *pq, *pk, *pv, *pa;
    cudaGetSymbolAddress(&pq, g_q);
    cudaGetSymbolAddress(&pk, g_k);
    cudaGetSymbolAddress(&pv, g_v);
    cudaGetSymbolAddress(&pa, g_att);

    cudaFuncSetAttribute(attn_kernel,
                         cudaFuncAttributeMaxDynamicSharedMemorySize,
                         ATT_SMEM_BYTES);

    dim3 gemm_grid(DMODEL / 128, ROWS / 128);   // (16, 32)

    sgemm_kernel<<<gemm_grid, 256>>>(x, Wq, (float*)pq, ROWS, DMODEL, DMODEL, nullptr);
    sgemm_kernel<<<gemm_grid, 256>>>(x, Wk, (float*)pk, ROWS, DMODEL, DMODEL, nullptr);
    sgemm_kernel<<<gemm_grid, 256>>>(x, Wv, (float*)pv, ROWS, DMODEL, DMODEL, nullptr);

    int rope_pairs = BATCH * SEQ * HEADS * (DH / 2);   // 4194304
    rope_kernel<<<rope_pairs / 256, 256>>>((float*)pq, qr, 0.08838834764831845f);
    rope_kernel<<<rope_pairs / 256, 256>>>((float*)pk, kr, 1.0f);

    attn_kernel<<<dim3(SEQ / 64, BATCH * HEADS), 256, ATT_SMEM_BYTES>>>(
        (const float*)pq, (const float*)pk, (const float*)pv, (float*)pa);

    sgemm_kernel<<<gemm_grid, 256>>>((const float*)pa, Wo, out, ROWS, DMODEL, DMODEL, bo);
}

// round 3
// speedup vs baseline: 1.3682x; 1.3682x over previous
#include <cuda_runtime.h>
#include <cuda_bf16.h>
#include <cstdint>

// ============================================================================
// AttentionWithRoPE — round 2 resubmit (infra failure last round): tensor-core
// projections via bf16 hi/lo split GEMM (K'=3K), fp32 flash attention.
//   B=2, N=2048, D=2048, H=16, Dh=128
//     A' = [Ahi | Alo | Ahi]  (M x 6144)
//     B' = [Bhi ; Bhi ; Blo]  (6144 x N)
//     C  = A'@B'  (fp32 accum)  ~= exact fp32 GEMM to ~1e-5 rel
// ============================================================================

#define BATCH   2
#define SEQ     2048
#define DMODEL  2048
#define HEADS   16
#define DH      128
#define ROWS    (BATCH * SEQ)          // 4096
#define KSPLIT  (3 * DMODEL)           // 6144

// ---- scratch (static __device__, no allocations) ----
__device__ float g_q[ROWS * DMODEL];
__device__ float g_k[ROWS * DMODEL];
__device__ float g_v[ROWS * DMODEL];
__device__ float g_att[ROWS * DMODEL];
__device__ __nv_bfloat16 g_a  [ROWS * KSPLIT];      // split activations (x, then att)
__device__ __nv_bfloat16 g_wq [KSPLIT * DMODEL];
__device__ __nv_bfloat16 g_wk [KSPLIT * DMODEL];
__device__ __nv_bfloat16 g_wv [KSPLIT * DMODEL];
__device__ __nv_bfloat16 g_wo [KSPLIT * DMODEL];

// ---- packed f32x2 helpers (attention) ----
__device__ __forceinline__ unsigned long long pack2(float lo, float hi) {
    unsigned long long d;
    asm("mov.b64 %0, {%1, %2};" : "=l"(d) : "f"(lo), "f"(hi));
    return d;
}
__device__ __forceinline__ void unpack2(unsigned long long v, float& lo, float& hi) {
    asm("mov.b64 {%0, %1}, %2;" : "=f"(lo), "=f"(hi) : "l"(v));
}
__device__ __forceinline__ unsigned long long ffma2(unsigned long long a,
                                                    unsigned long long b,
                                                    unsigned long long c) {
    unsigned long long d;
    asm("fma.rn.f32x2 %0, %1, %2, %3;" : "=l"(d) : "l"(a), "l"(b), "l"(c));
    return d;
}
__device__ __forceinline__ unsigned long long fmul2(unsigned long long a,
                                                    unsigned long long b) {
    unsigned long long d;
    asm("mul.rn.f32x2 %0, %1, %2;" : "=l"(d) : "l"(a), "l"(b));
    return d;
}

// ============================================================================
// hi/lo split kernels
// ============================================================================
__global__ __launch_bounds__(256)
void split_a_kernel(const float* __restrict__ X, __nv_bfloat16* __restrict__ A,
                    int R) {
    int i = blockIdx.x * blockDim.x + threadIdx.x;
    if (i >= R * DMODEL) return;
    int r = i / DMODEL, c = i % DMODEL;
    float x = X[i];
    __nv_bfloat16 hi = __float2bfloat16(x);
    __nv_bfloat16 lo = __float2bfloat16(x - __bfloat162float(hi));
    __nv_bfloat16* row = A + (size_t)r * KSPLIT;
    row[c]              = hi;
    row[DMODEL + c]     = lo;
    row[2 * DMODEL + c] = hi;
}
__global__ __launch_bounds__(256)
void split_b_kernel(const float* __restrict__ W, __nv_bfloat16* __restrict__ Bo) {
    int i = blockIdx.x * blockDim.x + threadIdx.x;
    if (i >= DMODEL * DMODEL) return;
    float w = W[i];
    __nv_bfloat16 hi = __float2bfloat16(w);
    __nv_bfloat16 lo = __float2bfloat16(w - __bfloat162float(hi));
    Bo[i]                                 = hi;
    Bo[(size_t)DMODEL * DMODEL + i]       = hi;
    Bo[(size_t)2 * DMODEL * DMODEL + i]   = lo;
}

// ============================================================================
// bf16 tensor-core GEMM: C[M,N] = A[M,K] @ B[K,N] (+bias), fp32 accum.
// BM=BN=128, BK=32, 256 threads (8 warps as 2m x 4n, warp tile 64x32).
// 4-stage cp.async pipeline; smem pitches A=40, B=136 elems (conflict-free).
// ============================================================================
#define GBM 128
#define GBN 128
#define GBK 32
#define GSTAGES 4
#define APITCH 40
#define BPITCH 136
#define A_STAGE_ELEMS (GBM * APITCH)   // 5120
#define B_STAGE_ELEMS (GBK * BPITCH)   // 4352
#define GEMM_SMEM_BYTES (GSTAGES * (A_STAGE_ELEMS + B_STAGE_ELEMS) * 2)  // 75776

__device__ __forceinline__ void cp16(uint32_t smem_addr, const void* gptr) {
    asm volatile("cp.async.cg.shared.global [%0], [%1], 16;"
                 :: "r"(smem_addr), "l"(gptr));
}
__device__ __forceinline__ void cp_commit() {
    asm volatile("cp.async.commit_group;");
}
template <int Nwait>
__device__ __forceinline__ void cp_wait() {
    asm volatile("cp.async.wait_group %0;" :: "n"(Nwait));
}
__device__ __forceinline__ void ldsm_x4(uint32_t& r0, uint32_t& r1,
                                        uint32_t& r2, uint32_t& r3,
                                        uint32_t addr) {
    asm volatile("ldmatrix.sync.aligned.m8n8.x4.shared.b16 {%0,%1,%2,%3}, [%4];"
                 : "=r"(r0), "=r"(r1), "=r"(r2), "=r"(r3) : "r"(addr));
}
__device__ __forceinline__ void ldsm_x4_t(uint32_t& r0, uint32_t& r1,
                                          uint32_t& r2, uint32_t& r3,
                                          uint32_t addr) {
    asm volatile("ldmatrix.sync.aligned.m8n8.x4.trans.shared.b16 {%0,%1,%2,%3}, [%4];"
                 : "=r"(r0), "=r"(r1), "=r"(r2), "=r"(r3) : "r"(addr));
}
__device__ __forceinline__ void mma16816(float& c0, float& c1, float& c2, float& c3,
                                         uint32_t a0, uint32_t a1, uint32_t a2,
                                         uint32_t a3, uint32_t b0, uint32_t b1) {
    asm volatile(
        "mma.sync.aligned.m16n8k16.row.col.f32.bf16.bf16.f32 "
        "{%0,%1,%2,%3}, {%4,%5,%6,%7}, {%8,%9}, {%0,%1,%2,%3};"
        : "+f"(c0), "+f"(c1), "+f"(c2), "+f"(c3)
        : "r"(a0), "r"(a1), "r"(a2), "r"(a3), "r"(b0), "r"(b1));
}

__global__ __launch_bounds__(256, 1)
void gemm_bf16_kernel(const __nv_bfloat16* __restrict__ A,
                      const __nv_bfloat16* __restrict__ B,
                      float* __restrict__ C,
                      int M, int N, int K,
                      const float* __restrict__ bias) {
    extern __shared__ __nv_bfloat16 sm[];
    __nv_bfloat16* sA = sm;
    __nv_bfloat16* sB = sm + GSTAGES * A_STAGE_ELEMS;

    const int tid  = threadIdx.x;
    const int warp = tid >> 5;
    const int lane = tid & 31;
    const int wm = warp >> 2;
    const int wn = warp & 3;
    const int bx = blockIdx.x;
    const int by = blockIdx.y;

    const int at_row   = tid >> 2;
    const int at_chunk = (tid & 3) << 3;
    const int bt_row   = tid >> 4;
    const int bt_chunk = (tid & 15) << 3;

    const __nv_bfloat16* Ag = A + (size_t)(by * GBM + at_row) * K + at_chunk;
    const __nv_bfloat16* Bg = B + (size_t)bt_row * N + bx * GBN + bt_chunk;

    uint32_t sA_u32 = (uint32_t)__cvta_generic_to_shared(sA);
    uint32_t sB_u32 = (uint32_t)__cvta_generic_to_shared(sB);

    auto load_tile = [&](int stage, int k0) {
        uint32_t a_dst = sA_u32 + (stage * A_STAGE_ELEMS + at_row * APITCH + at_chunk) * 2;
        cp16(a_dst,                       Ag + k0);
        cp16(a_dst + 64 * APITCH * 2,     Ag + (size_t)64 * K + k0);
        uint32_t b_dst = sB_u32 + (stage * B_STAGE_ELEMS + bt_row * BPITCH + bt_chunk) * 2;
        cp16(b_dst,                       Bg + (size_t)k0 * N);
        cp16(b_dst + 16 * BPITCH * 2,     Bg + (size_t)(k0 + 16) * N);
    };

    float acc[4][4][4];
#pragma unroll
    for (int i = 0; i < 4; i++)
#pragma unroll
        for (int j = 0; j < 4; j++)
#pragma unroll
            for (int r = 0; r < 4; r++) acc[i][j][r] = 0.0f;

    const int KT = K / GBK;

#pragma unroll
    for (int s = 0; s < GSTAGES - 1; s++) { load_tile(s, s * GBK); cp_commit(); }

    const int a_lrow = (lane & 15);
    const int a_lcol = (lane >> 4) << 3;

    for (int kt = 0; kt < KT; kt++) {
        cp_wait<GSTAGES - 2>();
        __syncthreads();

        const int st = kt & (GSTAGES - 1);
        uint32_t aBase = sA_u32 + (st * A_STAGE_ELEMS) * 2;
        uint32_t bBase = sB_u32 + (st * B_STAGE_ELEMS) * 2;

#pragma unroll
        for (int ks = 0; ks < 2; ks++) {
            uint32_t a[4][4];
#pragma unroll
            for (int i = 0; i < 4; i++) {
                int row = wm * 64 + i * 16 + a_lrow;
                int col = ks * 16 + a_lcol;
                ldsm_x4(a[i][0], a[i][1], a[i][2], a[i][3],
                        aBase + (row * APITCH + col) * 2);
            }
            uint32_t b[4][2];
#pragma unroll
            for (int j2 = 0; j2 < 2; j2++) {
                int row = ks * 16 + a_lrow;
                int col = wn * 32 + j2 * 16 + a_lcol;
                uint32_t r0, r1, r2, r3;
                ldsm_x4_t(r0, r1, r2, r3, bBase + (row * BPITCH + col) * 2);
                b[2 * j2][0] = r0; b[2 * j2][1] = r1;
                b[2 * j2 + 1][0] = r2; b[2 * j2 + 1][1] = r3;
            }
#pragma unroll
            for (int i = 0; i < 4; i++)
#pragma unroll
                for (int j = 0; j < 4; j++)
                    mma16816(acc[i][j][0], acc[i][j][1], acc[i][j][2], acc[i][j][3],
                             a[i][0], a[i][1], a[i][2], a[i][3],
                             b[j][0], b[j][1]);
        }

        __syncthreads();
        int lt = kt + GSTAGES - 1;
        if (lt < KT) load_tile(lt & (GSTAGES - 1), lt * GBK);
        cp_commit();
    }

    const int row_base = by * GBM + wm * 64 + (lane >> 2);
    const int col_base = bx * GBN + wn * 32 + (lane & 3) * 2;
#pragma unroll
    for (int i = 0; i < 4; i++) {
#pragma unroll
        for (int j = 0; j < 4; j++) {
            int c = col_base + j * 8;
            float b0 = bias ? bias[c]     : 0.0f;
            float b1 = bias ? bias[c + 1] : 0.0f;
            float* p0 = C + (size_t)(row_base + i * 16) * N + c;
            float* p1 = C + (size_t)(row_base + i * 16 + 8) * N + c;
            p0[0] = acc[i][j][0] + b0; p0[1] = acc[i][j][1] + b1;
            p1[0] = acc[i][j][2] + b0; p1[1] = acc[i][j][3] + b1;
        }
    }
}

// ============================================================================
// RoPE (in-place on [B,N,H*Dh]; rope table [B,N,Dh] broadcast over heads)
// ============================================================================
__global__ __launch_bounds__(256)
void rope_kernel(float* __restrict__ X, const float* __restrict__ rope,
                 float scale) {
    int i = blockIdx.x * blockDim.x + threadIdx.x;
    int p  = i & 63;
    int h  = (i >> 6) & 15;
    int bn = i >> 10;
    float rr = rope[bn * DH + 2 * p];
    float ri = rope[bn * DH + 2 * p + 1];
    float* base = X + (size_t)bn * DMODEL + h * DH + 2 * p;
    float xr = base[0] * scale;
    float xi = base[1] * scale;
    base[0] = xr * rr - xi * ri;
    base[1] = xr * ri + xi * rr;
}

// ============================================================================
// Flash attention (fp32 f32x2), unchanged from round 1 (passed, 1.05e-6).
// ============================================================================
#define ATT_QS_ELEMS  (64 * 129)
#define ATT_PS_ELEMS  (64 * 65)
#define ATT_SMEM_BYTES ((2 * ATT_QS_ELEMS + ATT_PS_ELEMS) * 4)

__device__ __forceinline__ float redmax16(float v) {
    v = fmaxf(v, __shfl_xor_sync(0xffffffffu, v, 1, 16));
    v = fmaxf(v, __shfl_xor_sync(0xffffffffu, v, 2, 16));
    v = fmaxf(v, __shfl_xor_sync(0xffffffffu, v, 4, 16));
    v = fmaxf(v, __shfl_xor_sync(0xffffffffu, v, 8, 16));
    return v;
}
__device__ __forceinline__ float redsum16(float v) {
    v += __shfl_xor_sync(0xffffffffu, v, 1, 16);
    v += __shfl_xor_sync(0xffffffffu, v, 2, 16);
    v += __shfl_xor_sync(0xffffffffu, v, 4, 16);
    v += __shfl_xor_sync(0xffffffffu, v, 8, 16);
    return v;
}

__device__ __forceinline__ void load_tile_64x128(float* dst, const float* src,
                                                 int tid) {
#pragma unroll
    for (int it = 0; it < 8; it++) {
        int idx = tid + it * 256;
        int r   = idx >> 5;
        int c4  = (idx & 31) << 2;
        float4 v4 = *(const float4*)(src + (size_t)r * DMODEL + c4);
        float* d = dst + r * 129 + c4;
        d[0] = v4.x; d[1] = v4.y; d[2] = v4.z; d[3] = v4.w;
    }
}

__global__ __launch_bounds__(256, 2)
void attn_kernel(const float* __restrict__ Q, const float* __restrict__ K,
                 const float* __restrict__ V, float* __restrict__ O) {
    extern __shared__ float smf[];
    float* Qs  = smf;
    float* KVs = smf + ATT_QS_ELEMS;
    float* Ps  = smf + 2 * ATT_QS_ELEMS;

    const int tid = threadIdx.x;
    const int tx = tid & 15;
    const int ty = tid >> 4;
    const int qt = blockIdx.x;
    const int bh = blockIdx.y;
    const int b  = bh >> 4;
    const int h  = bh & 15;

    const float* Qg = Q + ((size_t)b * SEQ + qt * 64) * DMODEL + h * DH;
    const float* Kg = K + ((size_t)b * SEQ) * DMODEL + h * DH;
    const float* Vg = V + ((size_t)b * SEQ) * DMODEL + h * DH;
    float*       Og = O + ((size_t)b * SEQ + qt * 64) * DMODEL + h * DH;

    load_tile_64x128(Qs, Qg, tid);

    const float sscale = 0.08838834764831845f;

    float m_i[4], l_i[4];
    unsigned long long Oacc[4][4];
#pragma unroll
    for (int i = 0; i < 4; i++) {
        m_i[i] = -1e30f;
        l_i[i] = 0.0f;
#pragma unroll
        for (int j = 0; j < 4; j++) Oacc[i][j] = 0ull;
    }

    int qb[4], kb[4];
#pragma unroll
    for (int i = 0; i < 4; i++) qb[i] = (4 * ty + i) * 129;
#pragma unroll
    for (int j = 0; j < 4; j++) kb[j] = (4 * tx + j) * 129;

    for (int kt = 0; kt < SEQ / 64; kt++) {
        __syncthreads();
        load_tile_64x128(KVs, Kg + (size_t)(kt * 64) * DMODEL, tid);
        __syncthreads();

        unsigned long long S2[4][2];
#pragma unroll
        for (int i = 0; i < 4; i++) { S2[i][0] = 0ull; S2[i][1] = 0ull; }
#pragma unroll 4
        for (int d = 0; d < DH; d++) {
            float b0 = KVs[kb[0] + d], b1 = KVs[kb[1] + d];
            float b2 = KVs[kb[2] + d], b3 = KVs[kb[3] + d];
            unsigned long long bp0 = pack2(b0, b1);
            unsigned long long bp1 = pack2(b2, b3);
#pragma unroll
            for (int i = 0; i < 4; i++) {
                float a = Qs[qb[i] + d];
                unsigned long long ad = pack2(a, a);
                S2[i][0] = ffma2(ad, bp0, S2[i][0]);
                S2[i][1] = ffma2(ad, bp1, S2[i][1]);
            }
        }

#pragma unroll
        for (int i = 0; i < 4; i++) {
            float s0, s1, s2, s3;
            unpack2(S2[i][0], s0, s1);
            unpack2(S2[i][1], s2, s3);
            s0 *= sscale; s1 *= sscale; s2 *= sscale; s3 *= sscale;
            float rm = fmaxf(fmaxf(s0, s1), fmaxf(s2, s3));
            rm = redmax16(rm);
            float mn = fmaxf(m_i[i], rm);
            float alpha = __expf(m_i[i] - mn);
            float p0 = __expf(s0 - mn);
            float p1 = __expf(s1 - mn);
            float p2 = __expf(s2 - mn);
            float p3 = __expf(s3 - mn);
            float rs = redsum16(p0 + p1 + p2 + p3);
            l_i[i] = l_i[i] * alpha + rs;
            m_i[i] = mn;
            float* prow = &Ps[(4 * ty + i) * 65 + 4 * tx];
            prow[0] = p0; prow[1] = p1; prow[2] = p2; prow[3] = p3;
            unsigned long long ad = pack2(alpha, alpha);
#pragma unroll
            for (int j = 0; j < 4; j++) Oacc[i][j] = fmul2(Oacc[i][j], ad);
        }

        __syncthreads();
        load_tile_64x128(KVs, Vg + (size_t)(kt * 64) * DMODEL, tid);
        __syncthreads();

#pragma unroll 2
        for (int kk = 0; kk < 64; kk++) {
            const float* vrow = &KVs[kk * 129 + tx];
            unsigned long long v0 = pack2(vrow[0],  vrow[16]);
            unsigned long long v1 = pack2(vrow[32], vrow[48]);
            unsigned long long v2 = pack2(vrow[64], vrow[80]);
            unsigned long long v3 = pack2(vrow[96], vrow[112]);
#pragma unroll
            for (int i = 0; i < 4; i++) {
                float p = Ps[(4 * ty + i) * 65 + kk];
                unsigned long long pd = pack2(p, p);
                Oacc[i][0] = ffma2(pd, v0, Oacc[i][0]);
                Oacc[i][1] = ffma2(pd, v1, Oacc[i][1]);
                Oacc[i][2] = ffma2(pd, v2, Oacc[i][2]);
                Oacc[i][3] = ffma2(pd, v3, Oacc[i][3]);
            }
        }
    }

#pragma unroll
    for (int i = 0; i < 4; i++) {
        float inv = 1.0f / l_i[i];
        float* orow = Og + (size_t)(4 * ty + i) * DMODEL;
#pragma unroll
        for (int j = 0; j < 4; j++) {
            float lo, hi;
            unpack2(Oacc[i][j], lo, hi);
            orow[tx + 32 * j]      = lo * inv;
            orow[tx + 32 * j + 16] = hi * inv;
        }
    }
}

// ============================================================================
// host
// ============================================================================
extern "C" void kernel_launch(void* const* d_in, const int* in_sizes, int n_in,
                              void* d_out, int out_size) {
    const float* x   = (const float*)d_in[0];
    const float* qr  = (const float*)d_in[1];
    const float* kr  = (const float*)d_in[2];
    const float* Wq  = (const float*)d_in[3];
    const float* Wk  = (const float*)d_in[4];
    const float* Wv  = (const float*)d_in[5];
    const float* Wo  = (const float*)d_in[6];
    const float* bo  = (const float*)d_in[7];
    float* out = (float*)d_out;

    void *pq, *pk, *pv, *pa, *pab, *pwq, *pwk, *pwv, *pwo;
    cudaGetSymbolAddress(&pq,  g_q);
    cudaGetSymbolAddress(&pk,  g_k);
    cudaGetSymbolAddress(&pv,  g_v);
    cudaGetSymbolAddress(&pa,  g_att);
    cudaGetSymbolAddress(&pab, g_a);
    cudaGetSymbolAddress(&pwq, g_wq);
    cudaGetSymbolAddress(&pwk, g_wk);
    cudaGetSymbolAddress(&pwv, g_wv);
    cudaGetSymbolAddress(&pwo, g_wo);

    cudaFuncSetAttribute(attn_kernel,
                         cudaFuncAttributeMaxDynamicSharedMemorySize,
                         ATT_SMEM_BYTES);
    cudaFuncSetAttribute(gemm_bf16_kernel,
                         cudaFuncAttributeMaxDynamicSharedMemorySize,
                         GEMM_SMEM_BYTES);

    int wElems = DMODEL * DMODEL;
    split_b_kernel<<<(wElems + 255) / 256, 256>>>(Wq, (__nv_bfloat16*)pwq);
    split_b_kernel<<<(wElems + 255) / 256, 256>>>(Wk, (__nv_bfloat16*)pwk);
    split_b_kernel<<<(wElems + 255) / 256, 256>>>(Wv, (__nv_bfloat16*)pwv);
    split_b_kernel<<<(wElems + 255) / 256, 256>>>(Wo, (__nv_bfloat16*)pwo);

    int aElems = ROWS * DMODEL;
    split_a_kernel<<<(aElems + 255) / 256, 256>>>(x, (__nv_bfloat16*)pab, ROWS);

    dim3 ggrid(DMODEL / GBN, ROWS / GBM);   // (16, 32)
    gemm_bf16_kernel<<<ggrid, 256, GEMM_SMEM_BYTES>>>(
        (const __nv_bfloat16*)pab, (const __nv_bfloat16*)pwq, (float*)pq,
        ROWS, DMODEL, KSPLIT, nullptr);
    gemm_bf16_kernel<<<ggrid, 256, GEMM_SMEM_BYTES>>>(
        (const __nv_bfloat16*)pab, (const __nv_bfloat16*)pwk, (float*)pk,
        ROWS, DMODEL, KSPLIT, nullptr);
    gemm_bf16_kernel<<<ggrid, 256, GEMM_SMEM_BYTES>>>(
        (const __nv_bfloat16*)pab, (const __nv_bfloat16*)pwv, (float*)pv,
        ROWS, DMODEL, KSPLIT, nullptr);

    int rope_pairs = BATCH * SEQ * HEADS * (DH / 2);
    rope_kernel<<<rope_pairs / 256, 256>>>((float*)pq, qr, 0.08838834764831845f);
    rope_kernel<<<rope_pairs / 256, 256>>>((float*)pk, kr, 1.0f);

    attn_kernel<<<dim3(SEQ / 64, BATCH * HEADS), 256, ATT_SMEM_BYTES>>>(
        (const float*)pq, (const float*)pk, (const float*)pv, (float*)pa);

    split_a_kernel<<<(aElems + 255) / 256, 256>>>((const float*)pa,
                                                  (__nv_bfloat16*)pab, ROWS);
    gemm_bf16_kernel<<<ggrid, 256, GEMM_SMEM_BYTES>>>(
        (const __nv_bfloat16*)pab, (const __nv_bfloat16*)pwo, out,
        ROWS, DMODEL, KSPLIT, bo);
}

// round 4
// speedup vs baseline: 2.1368x; 1.5618x over previous
#include <cuda_runtime.h>
#include <cuda_bf16.h>
#include <cstdint>

// ============================================================================
// AttentionWithRoPE — round 4: tensor-core everything (sm_100a)
//   B=2, N=2048, D=2048, H=16, Dh=128
//   Projections: bf16 hi/lo split GEMM (K'=3K), mma.m16n8k16, unchanged.
//   Attention:   NEW — mma.m16n8k16 flash attention with hi/lo split:
//     S  = [Qhi|Qlo|Qhi] · [Khi|Khi|Klo]^T      (k'=384)
//     O += [Phi|Plo|Phi] · [Vhi;Vhi;Vlo]        (k'=192)
//   fp32 softmax in C-fragments; P re-packed as A-fragments (FA2 trick).
// ============================================================================

#define BATCH   2
#define SEQ     2048
#define DMODEL  2048
#define HEADS   16
#define DH      128
#define ROWS    (BATCH * SEQ)          // 4096
#define KSPLIT  (3 * DMODEL)           // 6144

// ---- scratch (static __device__, no allocations) ----
__device__ float g_q[ROWS * DMODEL];
__device__ float g_k[ROWS * DMODEL];
__device__ float g_v[ROWS * DMODEL];
__device__ float g_att[ROWS * DMODEL];
__device__ __nv_bfloat16 g_a  [ROWS * KSPLIT];
__device__ __nv_bfloat16 g_wq [KSPLIT * DMODEL];
__device__ __nv_bfloat16 g_wk [KSPLIT * DMODEL];
__device__ __nv_bfloat16 g_wv [KSPLIT * DMODEL];
__device__ __nv_bfloat16 g_wo [KSPLIT * DMODEL];

// ============================================================================
// common MMA / ldmatrix helpers
// ============================================================================
__device__ __forceinline__ void cp16(uint32_t smem_addr, const void* gptr) {
    asm volatile("cp.async.cg.shared.global [%0], [%1], 16;"
                 :: "r"(smem_addr), "l"(gptr));
}
__device__ __forceinline__ void cp_commit() {
    asm volatile("cp.async.commit_group;");
}
template <int Nwait>
__device__ __forceinline__ void cp_wait() {
    asm volatile("cp.async.wait_group %0;" :: "n"(Nwait));
}
__device__ __forceinline__ void ldsm_x4(uint32_t& r0, uint32_t& r1,
                                        uint32_t& r2, uint32_t& r3,
                                        uint32_t addr) {
    asm volatile("ldmatrix.sync.aligned.m8n8.x4.shared.b16 {%0,%1,%2,%3}, [%4];"
                 : "=r"(r0), "=r"(r1), "=r"(r2), "=r"(r3) : "r"(addr));
}
__device__ __forceinline__ void ldsm_x4_t(uint32_t& r0, uint32_t& r1,
                                          uint32_t& r2, uint32_t& r3,
                                          uint32_t addr) {
    asm volatile("ldmatrix.sync.aligned.m8n8.x4.trans.shared.b16 {%0,%1,%2,%3}, [%4];"
                 : "=r"(r0), "=r"(r1), "=r"(r2), "=r"(r3) : "r"(addr));
}
__device__ __forceinline__ void mma16816(float& c0, float& c1, float& c2, float& c3,
                                         uint32_t a0, uint32_t a1, uint32_t a2,
                                         uint32_t a3, uint32_t b0, uint32_t b1) {
    asm volatile(
        "mma.sync.aligned.m16n8k16.row.col.f32.bf16.bf16.f32 "
        "{%0,%1,%2,%3}, {%4,%5,%6,%7}, {%8,%9}, {%0,%1,%2,%3};"
        : "+f"(c0), "+f"(c1), "+f"(c2), "+f"(c3)
        : "r"(a0), "r"(a1), "r"(a2), "r"(a3), "r"(b0), "r"(b1));
}
__device__ __forceinline__ uint32_t pack_bf16x2(__nv_bfloat16 lo, __nv_bfloat16 hi) {
    __nv_bfloat162 p = __halves2bfloat162(lo, hi);
    return *reinterpret_cast<uint32_t*>(&p);
}

// ============================================================================
// hi/lo split kernels (projection GEMM inputs)
// ============================================================================
__global__ __launch_bounds__(256)
void split_a_kernel(const float* __restrict__ X, __nv_bfloat16* __restrict__ A,
                    int R) {
    int i = blockIdx.x * blockDim.x + threadIdx.x;
    if (i >= R * DMODEL) return;
    int r = i / DMODEL, c = i % DMODEL;
    float x = X[i];
    __nv_bfloat16 hi = __float2bfloat16(x);
    __nv_bfloat16 lo = __float2bfloat16(x - __bfloat162float(hi));
    __nv_bfloat16* row = A + (size_t)r * KSPLIT;
    row[c]              = hi;
    row[DMODEL + c]     = lo;
    row[2 * DMODEL + c] = hi;
}
__global__ __launch_bounds__(256)
void split_b_kernel(const float* __restrict__ W, __nv_bfloat16* __restrict__ Bo) {
    int i = blockIdx.x * blockDim.x + threadIdx.x;
    if (i >= DMODEL * DMODEL) return;
    float w = W[i];
    __nv_bfloat16 hi = __float2bfloat16(w);
    __nv_bfloat16 lo = __float2bfloat16(w - __bfloat162float(hi));
    Bo[i]                                 = hi;
    Bo[(size_t)DMODEL * DMODEL + i]       = hi;
    Bo[(size_t)2 * DMODEL * DMODEL + i]   = lo;
}

// ============================================================================
// bf16 tensor-core GEMM (projections) — unchanged from round 3 (verified).
// ============================================================================
#define GBM 128
#define GBN 128
#define GBK 32
#define GSTAGES 4
#define APITCH 40
#define BPITCH 136
#define A_STAGE_ELEMS (GBM * APITCH)
#define B_STAGE_ELEMS (GBK * BPITCH)
#define GEMM_SMEM_BYTES (GSTAGES * (A_STAGE_ELEMS + B_STAGE_ELEMS) * 2)

__global__ __launch_bounds__(256, 1)
void gemm_bf16_kernel(const __nv_bfloat16* __restrict__ A,
                      const __nv_bfloat16* __restrict__ B,
                      float* __restrict__ C,
                      int M, int N, int K,
                      const float* __restrict__ bias) {
    extern __shared__ __nv_bfloat16 sm[];
    __nv_bfloat16* sA = sm;
    __nv_bfloat16* sB = sm + GSTAGES * A_STAGE_ELEMS;

    const int tid  = threadIdx.x;
    const int warp = tid >> 5;
    const int lane = tid & 31;
    const int wm = warp >> 2;
    const int wn = warp & 3;
    const int bx = blockIdx.x;
    const int by = blockIdx.y;

    const int at_row   = tid >> 2;
    const int at_chunk = (tid & 3) << 3;
    const int bt_row   = tid >> 4;
    const int bt_chunk = (tid & 15) << 3;

    const __nv_bfloat16* Ag = A + (size_t)(by * GBM + at_row) * K + at_chunk;
    const __nv_bfloat16* Bg = B + (size_t)bt_row * N + bx * GBN + bt_chunk;

    uint32_t sA_u32 = (uint32_t)__cvta_generic_to_shared(sA);
    uint32_t sB_u32 = (uint32_t)__cvta_generic_to_shared(sB);

    auto load_tile = [&](int stage, int k0) {
        uint32_t a_dst = sA_u32 + (stage * A_STAGE_ELEMS + at_row * APITCH + at_chunk) * 2;
        cp16(a_dst,                       Ag + k0);
        cp16(a_dst + 64 * APITCH * 2,     Ag + (size_t)64 * K + k0);
        uint32_t b_dst = sB_u32 + (stage * B_STAGE_ELEMS + bt_row * BPITCH + bt_chunk) * 2;
        cp16(b_dst,                       Bg + (size_t)k0 * N);
        cp16(b_dst + 16 * BPITCH * 2,     Bg + (size_t)(k0 + 16) * N);
    };

    float acc[4][4][4];
#pragma unroll
    for (int i = 0; i < 4; i++)
#pragma unroll
        for (int j = 0; j < 4; j++)
#pragma unroll
            for (int r = 0; r < 4; r++) acc[i][j][r] = 0.0f;

    const int KT = K / GBK;

#pragma unroll
    for (int s = 0; s < GSTAGES - 1; s++) { load_tile(s, s * GBK); cp_commit(); }

    const int a_lrow = (lane & 15);
    const int a_lcol = (lane >> 4) << 3;

    for (int kt = 0; kt < KT; kt++) {
        cp_wait<GSTAGES - 2>();
        __syncthreads();

        const int st = kt & (GSTAGES - 1);
        uint32_t aBase = sA_u32 + (st * A_STAGE_ELEMS) * 2;
        uint32_t bBase = sB_u32 + (st * B_STAGE_ELEMS) * 2;

#pragma unroll
        for (int ks = 0; ks < 2; ks++) {
            uint32_t a[4][4];
#pragma unroll
            for (int i = 0; i < 4; i++) {
                int row = wm * 64 + i * 16 + a_lrow;
                int col = ks * 16 + a_lcol;
                ldsm_x4(a[i][0], a[i][1], a[i][2], a[i][3],
                        aBase + (row * APITCH + col) * 2);
            }
            uint32_t b[4][2];
#pragma unroll
            for (int j2 = 0; j2 < 2; j2++) {
                int row = ks * 16 + a_lrow;
                int col = wn * 32 + j2 * 16 + a_lcol;
                uint32_t r0, r1, r2, r3;
                ldsm_x4_t(r0, r1, r2, r3, bBase + (row * BPITCH + col) * 2);
                b[2 * j2][0] = r0; b[2 * j2][1] = r1;
                b[2 * j2 + 1][0] = r2; b[2 * j2 + 1][1] = r3;
            }
#pragma unroll
            for (int i = 0; i < 4; i++)
#pragma unroll
                for (int j = 0; j < 4; j++)
                    mma16816(acc[i][j][0], acc[i][j][1], acc[i][j][2], acc[i][j][3],
                             a[i][0], a[i][1], a[i][2], a[i][3],
                             b[j][0], b[j][1]);
        }

        __syncthreads();
        int lt = kt + GSTAGES - 1;
        if (lt < KT) load_tile(lt & (GSTAGES - 1), lt * GBK);
        cp_commit();
    }

    const int row_base = by * GBM + wm * 64 + (lane >> 2);
    const int col_base = bx * GBN + wn * 32 + (lane & 3) * 2;
#pragma unroll
    for (int i = 0; i < 4; i++) {
#pragma unroll
        for (int j = 0; j < 4; j++) {
            int c = col_base + j * 8;
            float b0 = bias ? bias[c]     : 0.0f;
            float b1 = bias ? bias[c + 1] : 0.0f;
            float* p0 = C + (size_t)(row_base + i * 16) * N + c;
            float* p1 = C + (size_t)(row_base + i * 16 + 8) * N + c;
            p0[0] = acc[i][j][0] + b0; p0[1] = acc[i][j][1] + b1;
            p1[0] = acc[i][j][2] + b0; p1[1] = acc[i][j][3] + b1;
        }
    }
}

// ============================================================================
// RoPE (in-place on [B,N,H*Dh]; rope table [B,N,Dh] broadcast over heads)
// ============================================================================
__global__ __launch_bounds__(256)
void rope_kernel(float* __restrict__ X, const float* __restrict__ rope,
                 float scale) {
    int i = blockIdx.x * blockDim.x + threadIdx.x;
    int p  = i & 63;
    int h  = (i >> 6) & 15;
    int bn = i >> 10;
    float rr = rope[bn * DH + 2 * p];
    float ri = rope[bn * DH + 2 * p + 1];
    float* base = X + (size_t)bn * DMODEL + h * DH + 2 * p;
    float xr = base[0] * scale;
    float xi = base[1] * scale;
    base[0] = xr * rr - xi * ri;
    base[1] = xr * ri + xi * rr;
}

// ============================================================================
// MMA flash attention, hi/lo split.
// Block: 128 queries x one (b,h); 8 warps x 16 rows; 64-key tiles.
// smem: Qhi/Qlo [128][136], Khi/Klo [64][136], Vhi/Vlo [64][136] bf16.
// ============================================================================
#define AQT   128
#define AKT   64
#define APIT  136
#define AQ_ELEMS  (AQT * APIT)     // 17408
#define AKV_ELEMS (AKT * APIT)     // 8704
#define ATT2_SMEM_BYTES ((2 * AQ_ELEMS + 4 * AKV_ELEMS) * 2)   // 139264

__device__ __forceinline__ void split_store4(__nv_bfloat16* hiP,
                                             __nv_bfloat16* loP, float4 v) {
    __nv_bfloat16 h0 = __float2bfloat16(v.x);
    __nv_bfloat16 h1 = __float2bfloat16(v.y);
    __nv_bfloat16 h2 = __float2bfloat16(v.z);
    __nv_bfloat16 h3 = __float2bfloat16(v.w);
    __nv_bfloat16 l0 = __float2bfloat16(v.x - __bfloat162float(h0));
    __nv_bfloat16 l1 = __float2bfloat16(v.y - __bfloat162float(h1));
    __nv_bfloat16 l2 = __float2bfloat16(v.z - __bfloat162float(h2));
    __nv_bfloat16 l3 = __float2bfloat16(v.w - __bfloat162float(h3));
    *(__nv_bfloat162*)(hiP)     = __halves2bfloat162(h0, h1);
    *(__nv_bfloat162*)(hiP + 2) = __halves2bfloat162(h2, h3);
    *(__nv_bfloat162*)(loP)     = __halves2bfloat162(l0, l1);
    *(__nv_bfloat162*)(loP + 2) = __halves2bfloat162(l2, l3);
}

__global__ __launch_bounds__(256, 1)
void attn_mma_kernel(const float* __restrict__ Q, const float* __restrict__ K,
                     const float* __restrict__ V, float* __restrict__ O) {
    extern __shared__ __nv_bfloat16 smb[];
    __nv_bfloat16* Qhi = smb;
    __nv_bfloat16* Qlo = smb + AQ_ELEMS;
    __nv_bfloat16* Khi = smb + 2 * AQ_ELEMS;
    __nv_bfloat16* Klo = Khi + AKV_ELEMS;
    __nv_bfloat16* Vhi = Klo + AKV_ELEMS;
    __nv_bfloat16* Vlo = Vhi + AKV_ELEMS;

    const int tid  = threadIdx.x;
    const int warp = tid >> 5;
    const int lane = tid & 31;
    const int qt = blockIdx.x;
    const int bh = blockIdx.y;
    const int b  = bh >> 4;
    const int h  = bh & 15;

    const float* Qg = Q + ((size_t)b * SEQ + qt * AQT) * DMODEL + h * DH;
    const float* Kg = K + ((size_t)b * SEQ) * DMODEL + h * DH;
    const float* Vg = V + ((size_t)b * SEQ) * DMODEL + h * DH;
    float*       Og = O + ((size_t)b * SEQ + qt * AQT) * DMODEL + h * DH;

    // ---- load + split Q (128x128) ----
#pragma unroll
    for (int it = 0; it < 16; it++) {
        int idx = tid + it * 256;
        int r = idx >> 5, c4 = (idx & 31) << 2;
        float4 v = *(const float4*)(Qg + (size_t)r * DMODEL + c4);
        split_store4(Qhi + r * APIT + c4, Qlo + r * APIT + c4, v);
    }

    uint32_t uQhi = (uint32_t)__cvta_generic_to_shared(Qhi);
    uint32_t uQlo = (uint32_t)__cvta_generic_to_shared(Qlo);
    uint32_t uKhi = (uint32_t)__cvta_generic_to_shared(Khi);
    uint32_t uKlo = (uint32_t)__cvta_generic_to_shared(Klo);
    uint32_t uVhi = (uint32_t)__cvta_generic_to_shared(Vhi);
    uint32_t uVlo = (uint32_t)__cvta_generic_to_shared(Vlo);

    const float sscale = 0.08838834764831845f;  // 1/sqrt(128)

    // per-thread softmax state: rows (warp*16 + lane/4) and (+8)
    float m0 = -1e30f, m1 = -1e30f, l0 = 0.0f, l1 = 0.0f;
    float oacc[16][4];
#pragma unroll
    for (int nt = 0; nt < 16; nt++)
#pragma unroll
        for (int e = 0; e < 4; e++) oacc[nt][e] = 0.0f;

    // ldmatrix lane-address components
    const int rowA = lane & 15;                      // A frags (Q)
    const int colA = (lane >> 4) << 3;
    const int rowK = (lane & 7) + ((lane >> 4) << 3); // K b-frags (non-trans)
    const int colK = ((lane >> 3) & 1) << 3;
    const int rowV = lane & 15;                      // V b-frags (trans)
    const int colV = (lane >> 4) << 3;

    const uint32_t qhiBase = uQhi + ((warp * 16 + rowA) * APIT) * 2;
    const uint32_t qloBase = uQlo + ((warp * 16 + rowA) * APIT) * 2;

    for (int kt = 0; kt < SEQ / AKT; kt++) {
        __syncthreads();   // prior S/PV reads of K/V done
        // ---- load + split K and V tiles (64x128 each) ----
#pragma unroll
        for (int it = 0; it < 8; it++) {
            int idx = tid + it * 256;
            int r = idx >> 5, c4 = (idx & 31) << 2;
            float4 kv = *(const float4*)(Kg + (size_t)(kt * AKT + r) * DMODEL + c4);
            split_store4(Khi + r * APIT + c4, Klo + r * APIT + c4, kv);
            float4 vv = *(const float4*)(Vg + (size_t)(kt * AKT + r) * DMODEL + c4);
            split_store4(Vhi + r * APIT + c4, Vlo + r * APIT + c4, vv);
        }
        __syncthreads();

        // ---- S = Q'K'^T : 16x64 per warp ----
        float s[8][4];
#pragma unroll
        for (int nt = 0; nt < 8; nt++)
#pragma unroll
            for (int e = 0; e < 4; e++) s[nt][e] = 0.0f;

#pragma unroll
        for (int ks = 0; ks < 8; ks++) {
            uint32_t ah[4], al[4];
            ldsm_x4(ah[0], ah[1], ah[2], ah[3],
                    qhiBase + (ks * 16 + colA) * 2);
            ldsm_x4(al[0], al[1], al[2], al[3],
                    qloBase + (ks * 16 + colA) * 2);
#pragma unroll
            for (int jn = 0; jn < 4; jn++) {
                uint32_t b0, b1, b2, b3;
                // Khi: terms Qhi*Khi and Qlo*Khi
                ldsm_x4(b0, b1, b2, b3,
                        uKhi + ((jn * 16 + rowK) * APIT + ks * 16 + colK) * 2);
                mma16816(s[2*jn][0], s[2*jn][1], s[2*jn][2], s[2*jn][3],
                         ah[0], ah[1], ah[2], ah[3], b0, b1);
                mma16816(s[2*jn+1][0], s[2*jn+1][1], s[2*jn+1][2], s[2*jn+1][3],
                         ah[0], ah[1], ah[2], ah[3], b2, b3);
                mma16816(s[2*jn][0], s[2*jn][1], s[2*jn][2], s[2*jn][3],
                         al[0], al[1], al[2], al[3], b0, b1);
                mma16816(s[2*jn+1][0], s[2*jn+1][1], s[2*jn+1][2], s[2*jn+1][3],
                         al[0], al[1], al[2], al[3], b2, b3);
                // Klo: term Qhi*Klo
                ldsm_x4(b0, b1, b2, b3,
                        uKlo + ((jn * 16 + rowK) * APIT + ks * 16 + colK) * 2);
                mma16816(s[2*jn][0], s[2*jn][1], s[2*jn][2], s[2*jn][3],
                         ah[0], ah[1], ah[2], ah[3], b0, b1);
                mma16816(s[2*jn+1][0], s[2*jn+1][1], s[2*jn+1][2], s[2*jn+1][3],
                         ah[0], ah[1], ah[2], ah[3], b2, b3);
            }
        }

        // ---- online softmax (rows lane/4 and lane/4+8) ----
        float tm0 = -1e30f, tm1 = -1e30f;
#pragma unroll
        for (int nt = 0; nt < 8; nt++) {
            s[nt][0] *= sscale; s[nt][1] *= sscale;
            s[nt][2] *= sscale; s[nt][3] *= sscale;
            tm0 = fmaxf(tm0, fmaxf(s[nt][0], s[nt][1]));
            tm1 = fmaxf(tm1, fmaxf(s[nt][2], s[nt][3]));
        }
        tm0 = fmaxf(tm0, __shfl_xor_sync(0xffffffffu, tm0, 1));
        tm0 = fmaxf(tm0, __shfl_xor_sync(0xffffffffu, tm0, 2));
        tm1 = fmaxf(tm1, __shfl_xor_sync(0xffffffffu, tm1, 1));
        tm1 = fmaxf(tm1, __shfl_xor_sync(0xffffffffu, tm1, 2));

        float mn0 = fmaxf(m0, tm0), mn1 = fmaxf(m1, tm1);
        float al0 = __expf(m0 - mn0), al1 = __expf(m1 - mn1);
        m0 = mn0; m1 = mn1;

        float rs0 = 0.0f, rs1 = 0.0f;
        uint32_t aPhi[4][4], aPlo[4][4];
#pragma unroll
        for (int nt = 0; nt < 8; nt++) {
            float p0 = __expf(s[nt][0] - mn0);
            float p1 = __expf(s[nt][1] - mn0);
            float p2 = __expf(s[nt][2] - mn1);
            float p3 = __expf(s[nt][3] - mn1);
            rs0 += p0 + p1; rs1 += p2 + p3;
            __nv_bfloat16 f0 = __float2bfloat16(p0);
            __nv_bfloat16 f1 = __float2bfloat16(p1);
            __nv_bfloat16 f2 = __float2bfloat16(p2);
            __nv_bfloat16 f3 = __float2bfloat16(p3);
            __nv_bfloat16 g0 = __float2bfloat16(p0 - __bfloat162float(f0));
            __nv_bfloat16 g1 = __float2bfloat16(p1 - __bfloat162float(f1));
            __nv_bfloat16 g2 = __float2bfloat16(p2 - __bfloat162float(f2));
            __nv_bfloat16 g3 = __float2bfloat16(p3 - __bfloat162float(f3));
            int t4 = nt >> 1, hh = (nt & 1) << 1;
            aPhi[t4][hh]     = pack_bf16x2(f0, f1);
            aPhi[t4][hh + 1] = pack_bf16x2(f2, f3);
            aPlo[t4][hh]     = pack_bf16x2(g0, g1);
            aPlo[t4][hh + 1] = pack_bf16x2(g2, g3);
        }
        rs0 += __shfl_xor_sync(0xffffffffu, rs0, 1);
        rs0 += __shfl_xor_sync(0xffffffffu, rs0, 2);
        rs1 += __shfl_xor_sync(0xffffffffu, rs1, 1);
        rs1 += __shfl_xor_sync(0xffffffffu, rs1, 2);
        l0 = l0 * al0 + rs0;
        l1 = l1 * al1 + rs1;

#pragma unroll
        for (int nt = 0; nt < 16; nt++) {
            oacc[nt][0] *= al0; oacc[nt][1] *= al0;
            oacc[nt][2] *= al1; oacc[nt][3] *= al1;
        }

        // ---- O += P'V' ----
#pragma unroll
        for (int k4 = 0; k4 < 4; k4++) {
#pragma unroll
            for (int jd = 0; jd < 8; jd++) {
                uint32_t b0, b1, b2, b3;
                ldsm_x4_t(b0, b1, b2, b3,
                          uVhi + ((k4 * 16 + rowV) * APIT + jd * 16 + colV) * 2);
                mma16816(oacc[2*jd][0], oacc[2*jd][1], oacc[2*jd][2], oacc[2*jd][3],
                         aPhi[k4][0], aPhi[k4][1], aPhi[k4][2], aPhi[k4][3], b0, b1);
                mma16816(oacc[2*jd+1][0], oacc[2*jd+1][1], oacc[2*jd+1][2], oacc[2*jd+1][3],
                         aPhi[k4][0], aPhi[k4][1], aPhi[k4][2], aPhi[k4][3], b2, b3);
                mma16816(oacc[2*jd][0], oacc[2*jd][1], oacc[2*jd][2], oacc[2*jd][3],
                         aPlo[k4][0], aPlo[k4][1], aPlo[k4][2], aPlo[k4][3], b0, b1);
                mma16816(oacc[2*jd+1][0], oacc[2*jd+1][1], oacc[2*jd+1][2], oacc[2*jd+1][3],
                         aPlo[k4][0], aPlo[k4][1], aPlo[k4][2], aPlo[k4][3], b2, b3);
                ldsm_x4_t(b0, b1, b2, b3,
                          uVlo + ((k4 * 16 + rowV) * APIT + jd * 16 + colV) * 2);
                mma16816(oacc[2*jd][0], oacc[2*jd][1], oacc[2*jd][2], oacc[2*jd][3],
                         aPhi[k4][0], aPhi[k4][1], aPhi[k4][2], aPhi[k4][3], b0, b1);
                mma16816(oacc[2*jd+1][0], oacc[2*jd+1][1], oacc[2*jd+1][2], oacc[2*jd+1][3],
                         aPhi[k4][0], aPhi[k4][1], aPhi[k4][2], aPhi[k4][3], b2, b3);
            }
        }
    }

    // ---- normalize + write ----
    float inv0 = 1.0f / l0, inv1 = 1.0f / l1;
    int row0 = warp * 16 + (lane >> 2);
    int c0 = (lane & 3) * 2;
#pragma unroll
    for (int nt = 0; nt < 16; nt++) {
        float* p0 = Og + (size_t)row0 * DMODEL + nt * 8 + c0;
        float* p1 = Og + (size_t)(row0 + 8) * DMODEL + nt * 8 + c0;
        p0[0] = oacc[nt][0] * inv0; p0[1] = oacc[nt][1] * inv0;
        p1[0] = oacc[nt][2] * inv1; p1[1] = oacc[nt][3] * inv1;
    }
}

// ============================================================================
// host
// ============================================================================
extern "C" void kernel_launch(void* const* d_in, const int* in_sizes, int n_in,
                              void* d_out, int out_size) {
    const float* x   = (const float*)d_in[0];
    const float* qr  = (const float*)d_in[1];
    const float* kr  = (const float*)d_in[2];
    const float* Wq  = (const float*)d_in[3];
    const float* Wk  = (const float*)d_in[4];
    const float* Wv  = (const float*)d_in[5];
    const float* Wo  = (const float*)d_in[6];
    const float* bo  = (const float*)d_in[7];
    float* out = (float*)d_out;

    void *pq, *pk, *pv, *pa, *pab, *pwq, *pwk, *pwv, *pwo;
    cudaGetSymbolAddress(&pq,  g_q);
    cudaGetSymbolAddress(&pk,  g_k);
    cudaGetSymbolAddress(&pv,  g_v);
    cudaGetSymbolAddress(&pa,  g_att);
    cudaGetSymbolAddress(&pab, g_a);
    cudaGetSymbolAddress(&pwq, g_wq);
    cudaGetSymbolAddress(&pwk, g_wk);
    cudaGetSymbolAddress(&pwv, g_wv);
    cudaGetSymbolAddress(&pwo, g_wo);

    cudaFuncSetAttribute(gemm_bf16_kernel,
                         cudaFuncAttributeMaxDynamicSharedMemorySize,
                         GEMM_SMEM_BYTES);
    cudaFuncSetAttribute(attn_mma_kernel,
                         cudaFuncAttributeMaxDynamicSharedMemorySize,
                         ATT2_SMEM_BYTES);

    int wElems = DMODEL * DMODEL;
    split_b_kernel<<<(wElems + 255) / 256, 256>>>(Wq, (__nv_bfloat16*)pwq);
    split_b_kernel<<<(wElems + 255) / 256, 256>>>(Wk, (__nv_bfloat16*)pwk);
    split_b_kernel<<<(wElems + 255) / 256, 256>>>(Wv, (__nv_bfloat16*)pwv);
    split_b_kernel<<<(wElems + 255) / 256, 256>>>(Wo, (__nv_bfloat16*)pwo);

    int aElems = ROWS * DMODEL;
    split_a_kernel<<<(aElems + 255) / 256, 256>>>(x, (__nv_bfloat16*)pab, ROWS);

    dim3 ggrid(DMODEL / GBN, ROWS / GBM);
    gemm_bf16_kernel<<<ggrid, 256, GEMM_SMEM_BYTES>>>(
        (const __nv_bfloat16*)pab, (const __nv_bfloat16*)pwq, (float*)pq,
        ROWS, DMODEL, KSPLIT, nullptr);
    gemm_bf16_kernel<<<ggrid, 256, GEMM_SMEM_BYTES>>>(
        (const __nv_bfloat16*)pab, (const __nv_bfloat16*)pwk, (float*)pk,
        ROWS, DMODEL, KSPLIT, nullptr);
    gemm_bf16_kernel<<<ggrid, 256, GEMM_SMEM_BYTES>>>(
        (const __nv_bfloat16*)pab, (const __nv_bfloat16*)pwv, (float*)pv,
        ROWS, DMODEL, KSPLIT, nullptr);

    int rope_pairs = BATCH * SEQ * HEADS * (DH / 2);
    rope_kernel<<<rope_pairs / 256, 256>>>((float*)pq, qr, 0.08838834764831845f);
    rope_kernel<<<rope_pairs / 256, 256>>>((float*)pk, kr, 1.0f);

    attn_mma_kernel<<<dim3(SEQ / AQT, BATCH * HEADS), 256, ATT2_SMEM_BYTES>>>(
        (const float*)pq, (const float*)pk, (const float*)pv, (float*)pa);

    split_a_kernel<<<(aElems + 255) / 256, 256>>>((const float*)pa,
                                                  (__nv_bfloat16*)pab, ROWS);
    gemm_bf16_kernel<<<ggrid, 256, GEMM_SMEM_BYTES>>>(
        (const __nv_bfloat16*)pab, (const __nv_bfloat16*)pwo, out,
        ROWS, DMODEL, KSPLIT, bo);
}

// round 7
// speedup vs baseline: 2.5152x; 1.1771x over previous
#include <cuda_runtime.h>
#include <cuda_bf16.h>
#include <cstdint>

// ============================================================================
// AttentionWithRoPE — round 6 resubmit (infra failure): mma.sync everywhere
// (harness targets sm_100, no tcgen05). Round-4 structure + occupancy-2 GEMM
// (3-stage cp.async) + attention epilogue writes the [hi|lo|hi] split directly.
//   B=2, N=2048, D=2048, H=16, Dh=128
// ============================================================================

#define BATCH   2
#define SEQ     2048
#define DMODEL  2048
#define HEADS   16
#define DH      128
#define ROWS    (BATCH * SEQ)          // 4096
#define KSPLIT  (3 * DMODEL)           // 6144

// ---- scratch (static __device__, no allocations) ----
__device__ float g_q[ROWS * DMODEL];
__device__ float g_k[ROWS * DMODEL];
__device__ float g_v[ROWS * DMODEL];
__device__ __nv_bfloat16 g_a  [ROWS * KSPLIT];
__device__ __nv_bfloat16 g_wq [KSPLIT * DMODEL];
__device__ __nv_bfloat16 g_wk [KSPLIT * DMODEL];
__device__ __nv_bfloat16 g_wv [KSPLIT * DMODEL];
__device__ __nv_bfloat16 g_wo [KSPLIT * DMODEL];

// ============================================================================
// common MMA / ldmatrix helpers
// ============================================================================
__device__ __forceinline__ void cp16(uint32_t smem_addr, const void* gptr) {
    asm volatile("cp.async.cg.shared.global [%0], [%1], 16;"
                 :: "r"(smem_addr), "l"(gptr));
}
__device__ __forceinline__ void cp_commit() {
    asm volatile("cp.async.commit_group;");
}
template <int Nwait>
__device__ __forceinline__ void cp_wait() {
    asm volatile("cp.async.wait_group %0;" :: "n"(Nwait));
}
__device__ __forceinline__ void ldsm_x4(uint32_t& r0, uint32_t& r1,
                                        uint32_t& r2, uint32_t& r3,
                                        uint32_t addr) {
    asm volatile("ldmatrix.sync.aligned.m8n8.x4.shared.b16 {%0,%1,%2,%3}, [%4];"
                 : "=r"(r0), "=r"(r1), "=r"(r2), "=r"(r3) : "r"(addr));
}
__device__ __forceinline__ void ldsm_x4_t(uint32_t& r0, uint32_t& r1,
                                          uint32_t& r2, uint32_t& r3,
                                          uint32_t addr) {
    asm volatile("ldmatrix.sync.aligned.m8n8.x4.trans.shared.b16 {%0,%1,%2,%3}, [%4];"
                 : "=r"(r0), "=r"(r1), "=r"(r2), "=r"(r3) : "r"(addr));
}
__device__ __forceinline__ void mma16816(float& c0, float& c1, float& c2, float& c3,
                                         uint32_t a0, uint32_t a1, uint32_t a2,
                                         uint32_t a3, uint32_t b0, uint32_t b1) {
    asm volatile(
        "mma.sync.aligned.m16n8k16.row.col.f32.bf16.bf16.f32 "
        "{%0,%1,%2,%3}, {%4,%5,%6,%7}, {%8,%9}, {%0,%1,%2,%3};"
        : "+f"(c0), "+f"(c1), "+f"(c2), "+f"(c3)
        : "r"(a0), "r"(a1), "r"(a2), "r"(a3), "r"(b0), "r"(b1));
}
__device__ __forceinline__ uint32_t pack_bf16x2(__nv_bfloat16 lo, __nv_bfloat16 hi) {
    __nv_bfloat162 p = __halves2bfloat162(lo, hi);
    return *reinterpret_cast<uint32_t*>(&p);
}

// ============================================================================
// hi/lo split kernels
// ============================================================================
__global__ __launch_bounds__(256)
void split_a_kernel(const float* __restrict__ X, __nv_bfloat16* __restrict__ A) {
    int i = blockIdx.x * blockDim.x + threadIdx.x;
    if (i >= ROWS * DMODEL) return;
    int r = i / DMODEL, c = i % DMODEL;
    float x = X[i];
    __nv_bfloat16 hi = __float2bfloat16(x);
    __nv_bfloat16 lo = __float2bfloat16(x - __bfloat162float(hi));
    __nv_bfloat16* row = A + (size_t)r * KSPLIT;
    row[c]              = hi;
    row[DMODEL + c]     = lo;
    row[2 * DMODEL + c] = hi;
}
__global__ __launch_bounds__(256)
void split_b_kernel(const float* __restrict__ W, __nv_bfloat16* __restrict__ Bo) {
    int i = blockIdx.x * blockDim.x + threadIdx.x;
    if (i >= DMODEL * DMODEL) return;
    float w = W[i];
    __nv_bfloat16 hi = __float2bfloat16(w);
    __nv_bfloat16 lo = __float2bfloat16(w - __bfloat162float(hi));
    Bo[i]                                 = hi;
    Bo[(size_t)DMODEL * DMODEL + i]       = hi;
    Bo[(size_t)2 * DMODEL * DMODEL + i]   = lo;
}

// ============================================================================
// bf16 tensor-core GEMM: BM=BN=128, BK=32, 256 threads, 3-stage cp.async,
// 2 CTAs/SM.
// ============================================================================
#define GBM 128
#define GBN 128
#define GBK 32
#define GSTAGES 3
#define APITCH 40
#define BPITCH 136
#define A_STAGE_ELEMS (GBM * APITCH)
#define B_STAGE_ELEMS (GBK * BPITCH)
#define GEMM_SMEM_BYTES (GSTAGES * (A_STAGE_ELEMS + B_STAGE_ELEMS) * 2)  // 56832

__global__ __launch_bounds__(256, 2)
void gemm_bf16_kernel(const __nv_bfloat16* __restrict__ A,
                      const __nv_bfloat16* __restrict__ B,
                      float* __restrict__ C,
                      int M, int N, int K,
                      const float* __restrict__ bias) {
    extern __shared__ __nv_bfloat16 sm[];
    __nv_bfloat16* sA = sm;
    __nv_bfloat16* sB = sm + GSTAGES * A_STAGE_ELEMS;

    const int tid  = threadIdx.x;
    const int warp = tid >> 5;
    const int lane = tid & 31;
    const int wm = warp >> 2;
    const int wn = warp & 3;
    const int bx = blockIdx.x;
    const int by = blockIdx.y;

    const int at_row   = tid >> 2;
    const int at_chunk = (tid & 3) << 3;
    const int bt_row   = tid >> 4;
    const int bt_chunk = (tid & 15) << 3;

    const __nv_bfloat16* Ag = A + (size_t)(by * GBM + at_row) * K + at_chunk;
    const __nv_bfloat16* Bg = B + (size_t)bt_row * N + bx * GBN + bt_chunk;

    uint32_t sA_u32 = (uint32_t)__cvta_generic_to_shared(sA);
    uint32_t sB_u32 = (uint32_t)__cvta_generic_to_shared(sB);

    auto load_tile = [&](int stage, int k0) {
        uint32_t a_dst = sA_u32 + (stage * A_STAGE_ELEMS + at_row * APITCH + at_chunk) * 2;
        cp16(a_dst,                       Ag + k0);
        cp16(a_dst + 64 * APITCH * 2,     Ag + (size_t)64 * K + k0);
        uint32_t b_dst = sB_u32 + (stage * B_STAGE_ELEMS + bt_row * BPITCH + bt_chunk) * 2;
        cp16(b_dst,                       Bg + (size_t)k0 * N);
        cp16(b_dst + 16 * BPITCH * 2,     Bg + (size_t)(k0 + 16) * N);
    };

    float acc[4][4][4];
#pragma unroll
    for (int i = 0; i < 4; i++)
#pragma unroll
        for (int j = 0; j < 4; j++)
#pragma unroll
            for (int r = 0; r < 4; r++) acc[i][j][r] = 0.0f;

    const int KT = K / GBK;

#pragma unroll
    for (int s = 0; s < GSTAGES - 1; s++) { load_tile(s, s * GBK); cp_commit(); }

    const int a_lrow = (lane & 15);
    const int a_lcol = (lane >> 4) << 3;

    int st = 0, lt_st = GSTAGES - 1;
    for (int kt = 0; kt < KT; kt++) {
        cp_wait<GSTAGES - 2>();
        __syncthreads();

        uint32_t aBase = sA_u32 + (st * A_STAGE_ELEMS) * 2;
        uint32_t bBase = sB_u32 + (st * B_STAGE_ELEMS) * 2;

#pragma unroll
        for (int ks = 0; ks < 2; ks++) {
            uint32_t a[4][4];
#pragma unroll
            for (int i = 0; i < 4; i++) {
                int row = wm * 64 + i * 16 + a_lrow;
                int col = ks * 16 + a_lcol;
                ldsm_x4(a[i][0], a[i][1], a[i][2], a[i][3],
                        aBase + (row * APITCH + col) * 2);
            }
            uint32_t b[4][2];
#pragma unroll
            for (int j2 = 0; j2 < 2; j2++) {
                int row = ks * 16 + a_lrow;
                int col = wn * 32 + j2 * 16 + a_lcol;
                uint32_t r0, r1, r2, r3;
                ldsm_x4_t(r0, r1, r2, r3, bBase + (row * BPITCH + col) * 2);
                b[2 * j2][0] = r0; b[2 * j2][1] = r1;
                b[2 * j2 + 1][0] = r2; b[2 * j2 + 1][1] = r3;
            }
#pragma unroll
            for (int i = 0; i < 4; i++)
#pragma unroll
                for (int j = 0; j < 4; j++)
                    mma16816(acc[i][j][0], acc[i][j][1], acc[i][j][2], acc[i][j][3],
                             a[i][0], a[i][1], a[i][2], a[i][3],
                             b[j][0], b[j][1]);
        }

        __syncthreads();
        int lt = kt + GSTAGES - 1;
        if (lt < KT) load_tile(lt_st, lt * GBK);
        cp_commit();
        if (++st == GSTAGES) st = 0;
        if (++lt_st == GSTAGES) lt_st = 0;
    }

    const int row_base = by * GBM + wm * 64 + (lane >> 2);
    const int col_base = bx * GBN + wn * 32 + (lane & 3) * 2;
#pragma unroll
    for (int i = 0; i < 4; i++) {
#pragma unroll
        for (int j = 0; j < 4; j++) {
            int c = col_base + j * 8;
            float b0 = bias ? bias[c]     : 0.0f;
            float b1 = bias ? bias[c + 1] : 0.0f;
            float* p0 = C + (size_t)(row_base + i * 16) * N + c;
            float* p1 = C + (size_t)(row_base + i * 16 + 8) * N + c;
            p0[0] = acc[i][j][0] + b0; p0[1] = acc[i][j][1] + b1;
            p1[0] = acc[i][j][2] + b0; p1[1] = acc[i][j][3] + b1;
        }
    }
}

// ============================================================================
// RoPE
// ============================================================================
__global__ __launch_bounds__(256)
void rope_kernel(float* __restrict__ X, const float* __restrict__ rope,
                 float scale) {
    int i = blockIdx.x * blockDim.x + threadIdx.x;
    int p  = i & 63;
    int h  = (i >> 6) & 15;
    int bn = i >> 10;
    float rr = rope[bn * DH + 2 * p];
    float ri = rope[bn * DH + 2 * p + 1];
    float* base = X + (size_t)bn * DMODEL + h * DH + 2 * p;
    float xr = base[0] * scale;
    float xi = base[1] * scale;
    base[0] = xr * rr - xi * ri;
    base[1] = xr * ri + xi * rr;
}

// ============================================================================
// MMA flash attention, hi/lo split (round-4 core, verified).
// Epilogue writes O directly as [hi|lo|hi] bf16 rows into g_a.
// ============================================================================
#define AQT   128
#define AKT   64
#define APIT  136
#define AQ_ELEMS  (AQT * APIT)
#define AKV_ELEMS (AKT * APIT)
#define ATT2_SMEM_BYTES ((2 * AQ_ELEMS + 4 * AKV_ELEMS) * 2)   // 139264

__device__ __forceinline__ void split_store4(__nv_bfloat16* hiP,
                                             __nv_bfloat16* loP, float4 v) {
    __nv_bfloat16 h0 = __float2bfloat16(v.x);
    __nv_bfloat16 h1 = __float2bfloat16(v.y);
    __nv_bfloat16 h2 = __float2bfloat16(v.z);
    __nv_bfloat16 h3 = __float2bfloat16(v.w);
    __nv_bfloat16 l0 = __float2bfloat16(v.x - __bfloat162float(h0));
    __nv_bfloat16 l1 = __float2bfloat16(v.y - __bfloat162float(h1));
    __nv_bfloat16 l2 = __float2bfloat16(v.z - __bfloat162float(h2));
    __nv_bfloat16 l3 = __float2bfloat16(v.w - __bfloat162float(h3));
    *(__nv_bfloat162*)(hiP)     = __halves2bfloat162(h0, h1);
    *(__nv_bfloat162*)(hiP + 2) = __halves2bfloat162(h2, h3);
    *(__nv_bfloat162*)(loP)     = __halves2bfloat162(l0, l1);
    *(__nv_bfloat162*)(loP + 2) = __halves2bfloat162(l2, l3);
}

__device__ __forceinline__ void store_split2(__nv_bfloat16* row, int c,
                                             float v0, float v1) {
    __nv_bfloat16 h0 = __float2bfloat16(v0);
    __nv_bfloat16 h1 = __float2bfloat16(v1);
    __nv_bfloat16 l0 = __float2bfloat16(v0 - __bfloat162float(h0));
    __nv_bfloat16 l1 = __float2bfloat16(v1 - __bfloat162float(h1));
    __nv_bfloat162 hp = __halves2bfloat162(h0, h1);
    *(__nv_bfloat162*)(row + c)              = hp;
    *(__nv_bfloat162*)(row + DMODEL + c)     = __halves2bfloat162(l0, l1);
    *(__nv_bfloat162*)(row + 2 * DMODEL + c) = hp;
}

__global__ __launch_bounds__(256, 1)
void attn_mma_kernel(const float* __restrict__ Q, const float* __restrict__ K,
                     const float* __restrict__ V,
                     __nv_bfloat16* __restrict__ Oa) {
    extern __shared__ __nv_bfloat16 smb[];
    __nv_bfloat16* Qhi = smb;
    __nv_bfloat16* Qlo = smb + AQ_ELEMS;
    __nv_bfloat16* Khi = smb + 2 * AQ_ELEMS;
    __nv_bfloat16* Klo = Khi + AKV_ELEMS;
    __nv_bfloat16* Vhi = Klo + AKV_ELEMS;
    __nv_bfloat16* Vlo = Vhi + AKV_ELEMS;

    const int tid  = threadIdx.x;
    const int warp = tid >> 5;
    const int lane = tid & 31;
    const int qt = blockIdx.x;
    const int bh = blockIdx.y;
    const int b  = bh >> 4;
    const int h  = bh & 15;

    const float* Qg = Q + ((size_t)b * SEQ + qt * AQT) * DMODEL + h * DH;
    const float* Kg = K + ((size_t)b * SEQ) * DMODEL + h * DH;
    const float* Vg = V + ((size_t)b * SEQ) * DMODEL + h * DH;
    __nv_bfloat16* Og = Oa + ((size_t)b * SEQ + qt * AQT) * KSPLIT + h * DH;

#pragma unroll
    for (int it = 0; it < 16; it++) {
        int idx = tid + it * 256;
        int r = idx >> 5, c4 = (idx & 31) << 2;
        float4 v = *(const float4*)(Qg + (size_t)r * DMODEL + c4);
        split_store4(Qhi + r * APIT + c4, Qlo + r * APIT + c4, v);
    }

    uint32_t uQhi = (uint32_t)__cvta_generic_to_shared(Qhi);
    uint32_t uQlo = (uint32_t)__cvta_generic_to_shared(Qlo);
    uint32_t uKhi = (uint32_t)__cvta_generic_to_shared(Khi);
    uint32_t uKlo = (uint32_t)__cvta_generic_to_shared(Klo);
    uint32_t uVhi = (uint32_t)__cvta_generic_to_shared(Vhi);
    uint32_t uVlo = (uint32_t)__cvta_generic_to_shared(Vlo);

    const float sscale = 0.08838834764831845f;

    float m0 = -1e30f, m1 = -1e30f, l0 = 0.0f, l1 = 0.0f;
    float oacc[16][4];
#pragma unroll
    for (int nt = 0; nt < 16; nt++)
#pragma unroll
        for (int e = 0; e < 4; e++) oacc[nt][e] = 0.0f;

    const int rowA = lane & 15;
    const int colA = (lane >> 4) << 3;
    const int rowK = (lane & 7) + ((lane >> 4) << 3);
    const int colK = ((lane >> 3) & 1) << 3;
    const int rowV = lane & 15;
    const int colV = (lane >> 4) << 3;

    const uint32_t qhiBase = uQhi + ((warp * 16 + rowA) * APIT) * 2;
    const uint32_t qloBase = uQlo + ((warp * 16 + rowA) * APIT) * 2;

    for (int kt = 0; kt < SEQ / AKT; kt++) {
        __syncthreads();
#pragma unroll
        for (int it = 0; it < 8; it++) {
            int idx = tid + it * 256;
            int r = idx >> 5, c4 = (idx & 31) << 2;
            float4 kv = *(const float4*)(Kg + (size_t)(kt * AKT + r) * DMODEL + c4);
            split_store4(Khi + r * APIT + c4, Klo + r * APIT + c4, kv);
            float4 vv = *(const float4*)(Vg + (size_t)(kt * AKT + r) * DMODEL + c4);
            split_store4(Vhi + r * APIT + c4, Vlo + r * APIT + c4, vv);
        }
        __syncthreads();

        float s[8][4];
#pragma unroll
        for (int nt = 0; nt < 8; nt++)
#pragma unroll
            for (int e = 0; e < 4; e++) s[nt][e] = 0.0f;

#pragma unroll
        for (int ks = 0; ks < 8; ks++) {
            uint32_t ah[4], al[4];
            ldsm_x4(ah[0], ah[1], ah[2], ah[3],
                    qhiBase + (ks * 16 + colA) * 2);
            ldsm_x4(al[0], al[1], al[2], al[3],
                    qloBase + (ks * 16 + colA) * 2);
#pragma unroll
            for (int jn = 0; jn < 4; jn++) {
                uint32_t b0, b1, b2, b3;
                ldsm_x4(b0, b1, b2, b3,
                        uKhi + ((jn * 16 + rowK) * APIT + ks * 16 + colK) * 2);
                mma16816(s[2*jn][0], s[2*jn][1], s[2*jn][2], s[2*jn][3],
                         ah[0], ah[1], ah[2], ah[3], b0, b1);
                mma16816(s[2*jn+1][0], s[2*jn+1][1], s[2*jn+1][2], s[2*jn+1][3],
                         ah[0], ah[1], ah[2], ah[3], b2, b3);
                mma16816(s[2*jn][0], s[2*jn][1], s[2*jn][2], s[2*jn][3],
                         al[0], al[1], al[2], al[3], b0, b1);
                mma16816(s[2*jn+1][0], s[2*jn+1][1], s[2*jn+1][2], s[2*jn+1][3],
                         al[0], al[1], al[2], al[3], b2, b3);
                ldsm_x4(b0, b1, b2, b3,
                        uKlo + ((jn * 16 + rowK) * APIT + ks * 16 + colK) * 2);
                mma16816(s[2*jn][0], s[2*jn][1], s[2*jn][2], s[2*jn][3],
                         ah[0], ah[1], ah[2], ah[3], b0, b1);
                mma16816(s[2*jn+1][0], s[2*jn+1][1], s[2*jn+1][2], s[2*jn+1][3],
                         ah[0], ah[1], ah[2], ah[3], b2, b3);
            }
        }

        float tm0 = -1e30f, tm1 = -1e30f;
#pragma unroll
        for (int nt = 0; nt < 8; nt++) {
            s[nt][0] *= sscale; s[nt][1] *= sscale;
            s[nt][2] *= sscale; s[nt][3] *= sscale;
            tm0 = fmaxf(tm0, fmaxf(s[nt][0], s[nt][1]));
            tm1 = fmaxf(tm1, fmaxf(s[nt][2], s[nt][3]));
        }
        tm0 = fmaxf(tm0, __shfl_xor_sync(0xffffffffu, tm0, 1));
        tm0 = fmaxf(tm0, __shfl_xor_sync(0xffffffffu, tm0, 2));
        tm1 = fmaxf(tm1, __shfl_xor_sync(0xffffffffu, tm1, 1));
        tm1 = fmaxf(tm1, __shfl_xor_sync(0xffffffffu, tm1, 2));

        float mn0 = fmaxf(m0, tm0), mn1 = fmaxf(m1, tm1);
        float al0 = __expf(m0 - mn0), al1 = __expf(m1 - mn1);
        m0 = mn0; m1 = mn1;

        float rs0 = 0.0f, rs1 = 0.0f;
        uint32_t aPhi[4][4], aPlo[4][4];
#pragma unroll
        for (int nt = 0; nt < 8; nt++) {
            float p0 = __expf(s[nt][0] - mn0);
            float p1 = __expf(s[nt][1] - mn0);
            float p2 = __expf(s[nt][2] - mn1);
            float p3 = __expf(s[nt][3] - mn1);
            rs0 += p0 + p1; rs1 += p2 + p3;
            __nv_bfloat16 f0 = __float2bfloat16(p0);
            __nv_bfloat16 f1 = __float2bfloat16(p1);
            __nv_bfloat16 f2 = __float2bfloat16(p2);
            __nv_bfloat16 f3 = __float2bfloat16(p3);
            __nv_bfloat16 g0 = __float2bfloat16(p0 - __bfloat162float(f0));
            __nv_bfloat16 g1 = __float2bfloat16(p1 - __bfloat162float(f1));
            __nv_bfloat16 g2 = __float2bfloat16(p2 - __bfloat162float(f2));
            __nv_bfloat16 g3 = __float2bfloat16(p3 - __bfloat162float(f3));
            int t4 = nt >> 1, hh = (nt & 1) << 1;
            aPhi[t4][hh]     = pack_bf16x2(f0, f1);
            aPhi[t4][hh + 1] = pack_bf16x2(f2, f3);
            aPlo[t4][hh]     = pack_bf16x2(g0, g1);
            aPlo[t4][hh + 1] = pack_bf16x2(g2, g3);
        }
        rs0 += __shfl_xor_sync(0xffffffffu, rs0, 1);
        rs0 += __shfl_xor_sync(0xffffffffu, rs0, 2);
        rs1 += __shfl_xor_sync(0xffffffffu, rs1, 1);
        rs1 += __shfl_xor_sync(0xffffffffu, rs1, 2);
        l0 = l0 * al0 + rs0;
        l1 = l1 * al1 + rs1;

#pragma unroll
        for (int nt = 0; nt < 16; nt++) {
            oacc[nt][0] *= al0; oacc[nt][1] *= al0;
            oacc[nt][2] *= al1; oacc[nt][3] *= al1;
        }

#pragma unroll
        for (int k4 = 0; k4 < 4; k4++) {
#pragma unroll
            for (int jd = 0; jd < 8; jd++) {
                uint32_t b0, b1, b2, b3;
                ldsm_x4_t(b0, b1, b2, b3,
                          uVhi + ((k4 * 16 + rowV) * APIT + jd * 16 + colV) * 2);
                mma16816(oacc[2*jd][0], oacc[2*jd][1], oacc[2*jd][2], oacc[2*jd][3],
                         aPhi[k4][0], aPhi[k4][1], aPhi[k4][2], aPhi[k4][3], b0, b1);
                mma16816(oacc[2*jd+1][0], oacc[2*jd+1][1], oacc[2*jd+1][2], oacc[2*jd+1][3],
                         aPhi[k4][0], aPhi[k4][1], aPhi[k4][2], aPhi[k4][3], b2, b3);
                mma16816(oacc[2*jd][0], oacc[2*jd][1], oacc[2*jd][2], oacc[2*jd][3],
                         aPlo[k4][0], aPlo[k4][1], aPlo[k4][2], aPlo[k4][3], b0, b1);
                mma16816(oacc[2*jd+1][0], oacc[2*jd+1][1], oacc[2*jd+1][2], oacc[2*jd+1][3],
                         aPlo[k4][0], aPlo[k4][1], aPlo[k4][2], aPlo[k4][3], b2, b3);
                ldsm_x4_t(b0, b1, b2, b3,
                          uVlo + ((k4 * 16 + rowV) * APIT + jd * 16 + colV) * 2);
                mma16816(oacc[2*jd][0], oacc[2*jd][1], oacc[2*jd][2], oacc[2*jd][3],
                         aPhi[k4][0], aPhi[k4][1], aPhi[k4][2], aPhi[k4][3], b0, b1);
                mma16816(oacc[2*jd+1][0], oacc[2*jd+1][1], oacc[2*jd+1][2], oacc[2*jd+1][3],
                         aPhi[k4][0], aPhi[k4][1], aPhi[k4][2], aPhi[k4][3], b2, b3);
            }
        }
    }

    // ---- normalize + write split [hi|lo|hi] rows of g_a ----
    float inv0 = 1.0f / l0, inv1 = 1.0f / l1;
    int row0 = warp * 16 + (lane >> 2);
    int c0 = (lane & 3) * 2;
#pragma unroll
    for (int nt = 0; nt < 16; nt++) {
        __nv_bfloat16* r0p = Og + (size_t)row0 * KSPLIT;
        __nv_bfloat16* r1p = Og + (size_t)(row0 + 8) * KSPLIT;
        store_split2(r0p, nt * 8 + c0, oacc[nt][0] * inv0, oacc[nt][1] * inv0);
        store_split2(r1p, nt * 8 + c0, oacc[nt][2] * inv1, oacc[nt][3] * inv1);
    }
}

// ============================================================================
// host
// ============================================================================
extern "C" void kernel_launch(void* const* d_in, const int* in_sizes, int n_in,
                              void* d_out, int out_size) {
    const float* x   = (const float*)d_in[0];
    const float* qr  = (const float*)d_in[1];
    const float* kr  = (const float*)d_in[2];
    const float* Wq  = (const float*)d_in[3];
    const float* Wk  = (const float*)d_in[4];
    const float* Wv  = (const float*)d_in[5];
    const float* Wo  = (const float*)d_in[6];
    const float* bo  = (const float*)d_in[7];
    float* out = (float*)d_out;

    void *pq, *pk, *pv, *pab, *pwq, *pwk, *pwv, *pwo;
    cudaGetSymbolAddress(&pq,  g_q);
    cudaGetSymbolAddress(&pk,  g_k);
    cudaGetSymbolAddress(&pv,  g_v);
    cudaGetSymbolAddress(&pab, g_a);
    cudaGetSymbolAddress(&pwq, g_wq);
    cudaGetSymbolAddress(&pwk, g_wk);
    cudaGetSymbolAddress(&pwv, g_wv);
    cudaGetSymbolAddress(&pwo, g_wo);

    cudaFuncSetAttribute(gemm_bf16_kernel,
                         cudaFuncAttributeMaxDynamicSharedMemorySize,
                         GEMM_SMEM_BYTES);
    cudaFuncSetAttribute(attn_mma_kernel,
                         cudaFuncAttributeMaxDynamicSharedMemorySize,
                         ATT2_SMEM_BYTES);

    int wElems = DMODEL * DMODEL;
    split_b_kernel<<<(wElems + 255) / 256, 256>>>(Wq, (__nv_bfloat16*)pwq);
    split_b_kernel<<<(wElems + 255) / 256, 256>>>(Wk, (__nv_bfloat16*)pwk);
    split_b_kernel<<<(wElems + 255) / 256, 256>>>(Wv, (__nv_bfloat16*)pwv);
    split_b_kernel<<<(wElems + 255) / 256, 256>>>(Wo, (__nv_bfloat16*)pwo);

    int aElems = ROWS * DMODEL;
    split_a_kernel<<<(aElems + 255) / 256, 256>>>(x, (__nv_bfloat16*)pab);

    dim3 ggrid(DMODEL / GBN, ROWS / GBM);   // (16, 32)
    gemm_bf16_kernel<<<ggrid, 256, GEMM_SMEM_BYTES>>>(
        (const __nv_bfloat16*)pab, (const __nv_bfloat16*)pwq, (float*)pq,
        ROWS, DMODEL, KSPLIT, nullptr);
    gemm_bf16_kernel<<<ggrid, 256, GEMM_SMEM_BYTES>>>(
        (const __nv_bfloat16*)pab, (const __nv_bfloat16*)pwk, (float*)pk,
        ROWS, DMODEL, KSPLIT, nullptr);
    gemm_bf16_kernel<<<ggrid, 256, GEMM_SMEM_BYTES>>>(
        (const __nv_bfloat16*)pab, (const __nv_bfloat16*)pwv, (float*)pv,
        ROWS, DMODEL, KSPLIT, nullptr);

    int rope_pairs = BATCH * SEQ * HEADS * (DH / 2);
    rope_kernel<<<rope_pairs / 256, 256>>>((float*)pq, qr, 0.08838834764831845f);
    rope_kernel<<<rope_pairs / 256, 256>>>((float*)pk, kr, 1.0f);

    // attention writes the [hi|lo|hi] split rows of g_a directly
    attn_mma_kernel<<<dim3(SEQ / AQT, BATCH * HEADS), 256, ATT2_SMEM_BYTES>>>(
        (const float*)pq, (const float*)pk, (const float*)pv,
        (__nv_bfloat16*)pab);

    gemm_bf16_kernel<<<ggrid, 256, GEMM_SMEM_BYTES>>>(
        (const __nv_bfloat16*)pab, (const __nv_bfloat16*)pwo, out,
        ROWS, DMODEL, KSPLIT, bo);
}

// round 11
// speedup vs baseline: 2.6110x; 1.0381x over previous
#include <cuda_runtime.h>
#include <cuda_bf16.h>
#include <cstdint>

// ============================================================================
// AttentionWithRoPE — round 11: FIX the B-fragment ldmatrix lane map in
// gemm_body (rounds 8-10 had the attention kernel's non-trans map pasted into
// the trans B load — deterministic wrong GEMM). Everything else = round 7
// verified components + QKV gridDim.z=3 fusion.
//   B=2, N=2048, D=2048, H=16, Dh=128
// ============================================================================

#define BATCH   2
#define SEQ     2048
#define DMODEL  2048
#define HEADS   16
#define DH      128
#define ROWS    (BATCH * SEQ)          // 4096
#define KSPLIT  (3 * DMODEL)           // 6144

// ---- scratch (static __device__, no allocations; 16B-aligned) ----
__device__ __align__(16) float g_q[ROWS * DMODEL];
__device__ __align__(16) float g_k[ROWS * DMODEL];
__device__ __align__(16) float g_v[ROWS * DMODEL];
__device__ __align__(16) __nv_bfloat16 g_a  [ROWS * KSPLIT];
__device__ __align__(16) __nv_bfloat16 g_wq [KSPLIT * DMODEL];
__device__ __align__(16) __nv_bfloat16 g_wk [KSPLIT * DMODEL];
__device__ __align__(16) __nv_bfloat16 g_wv [KSPLIT * DMODEL];
__device__ __align__(16) __nv_bfloat16 g_wo [KSPLIT * DMODEL];

// ============================================================================
// common MMA / ldmatrix helpers
// ============================================================================
__device__ __forceinline__ void cp16(uint32_t smem_addr, const void* gptr) {
    asm volatile("cp.async.cg.shared.global [%0], [%1], 16;"
                 :: "r"(smem_addr), "l"(gptr));
}
__device__ __forceinline__ void cp_commit() {
    asm volatile("cp.async.commit_group;");
}
template <int Nwait>
__device__ __forceinline__ void cp_wait() {
    asm volatile("cp.async.wait_group %0;" :: "n"(Nwait));
}
__device__ __forceinline__ void ldsm_x4(uint32_t& r0, uint32_t& r1,
                                        uint32_t& r2, uint32_t& r3,
                                        uint32_t addr) {
    asm volatile("ldmatrix.sync.aligned.m8n8.x4.shared.b16 {%0,%1,%2,%3}, [%4];"
                 : "=r"(r0), "=r"(r1), "=r"(r2), "=r"(r3) : "r"(addr));
}
__device__ __forceinline__ void ldsm_x4_t(uint32_t& r0, uint32_t& r1,
                                          uint32_t& r2, uint32_t& r3,
                                          uint32_t addr) {
    asm volatile("ldmatrix.sync.aligned.m8n8.x4.trans.shared.b16 {%0,%1,%2,%3}, [%4];"
                 : "=r"(r0), "=r"(r1), "=r"(r2), "=r"(r3) : "r"(addr));
}
__device__ __forceinline__ void mma16816(float& c0, float& c1, float& c2, float& c3,
                                         uint32_t a0, uint32_t a1, uint32_t a2,
                                         uint32_t a3, uint32_t b0, uint32_t b1) {
    asm volatile(
        "mma.sync.aligned.m16n8k16.row.col.f32.bf16.bf16.f32 "
        "{%0,%1,%2,%3}, {%4,%5,%6,%7}, {%8,%9}, {%0,%1,%2,%3};"
        : "+f"(c0), "+f"(c1), "+f"(c2), "+f"(c3)
        : "r"(a0), "r"(a1), "r"(a2), "r"(a3), "r"(b0), "r"(b1));
}
__device__ __forceinline__ uint32_t pack_bf16x2(__nv_bfloat16 lo, __nv_bfloat16 hi) {
    __nv_bfloat162 p = __halves2bfloat162(lo, hi);
    return *reinterpret_cast<uint32_t*>(&p);
}

// ============================================================================
// hi/lo split kernels — SCALAR (round-7 verified)
// ============================================================================
__global__ __launch_bounds__(256)
void split_a_kernel(const float* __restrict__ X, __nv_bfloat16* __restrict__ A) {
    int i = blockIdx.x * blockDim.x + threadIdx.x;
    if (i >= ROWS * DMODEL) return;
    int r = i / DMODEL, c = i % DMODEL;
    float x = X[i];
    __nv_bfloat16 hi = __float2bfloat16(x);
    __nv_bfloat16 lo = __float2bfloat16(x - __bfloat162float(hi));
    __nv_bfloat16* row = A + (size_t)r * KSPLIT;
    row[c]              = hi;
    row[DMODEL + c]     = lo;
    row[2 * DMODEL + c] = hi;
}
__global__ __launch_bounds__(256)
void split_b_kernel(const float* __restrict__ W, __nv_bfloat16* __restrict__ Bo) {
    int i = blockIdx.x * blockDim.x + threadIdx.x;
    if (i >= DMODEL * DMODEL) return;
    float w = W[i];
    __nv_bfloat16 hi = __float2bfloat16(w);
    __nv_bfloat16 lo = __float2bfloat16(w - __bfloat162float(hi));
    Bo[i]                                 = hi;
    Bo[(size_t)DMODEL * DMODEL + i]       = hi;
    Bo[(size_t)2 * DMODEL * DMODEL + i]   = lo;
}

// ============================================================================
// bf16 tensor-core GEMM body — round-7 verified (B-fragment map RESTORED).
// BM=BN=128, BK=32, 256 threads, 3-stage cp.async, double-sync, 2 CTAs/SM.
// ============================================================================
#define GBM 128
#define GBN 128
#define GBK 32
#define GSTAGES 3
#define APITCH 40
#define BPITCH 136
#define A_STAGE_ELEMS (GBM * APITCH)
#define B_STAGE_ELEMS (GBK * BPITCH)
#define GEMM_SMEM_BYTES (GSTAGES * (A_STAGE_ELEMS + B_STAGE_ELEMS) * 2)  // 56832

__device__ __forceinline__ void gemm_body(const __nv_bfloat16* __restrict__ A,
                                          const __nv_bfloat16* __restrict__ B,
                                          float* __restrict__ C,
                                          int M, int N, int K,
                                          const float* __restrict__ bias) {
    extern __shared__ __nv_bfloat16 sm[];
    __nv_bfloat16* sA = sm;
    __nv_bfloat16* sB = sm + GSTAGES * A_STAGE_ELEMS;

    const int tid  = threadIdx.x;
    const int warp = tid >> 5;
    const int lane = tid & 31;
    const int wm = warp >> 2;
    const int wn = warp & 3;
    const int bx = blockIdx.x;
    const int by = blockIdx.y;

    const int at_row   = tid >> 2;
    const int at_chunk = (tid & 3) << 3;
    const int bt_row   = tid >> 4;
    const int bt_chunk = (tid & 15) << 3;

    const __nv_bfloat16* Ag = A + (size_t)(by * GBM + at_row) * K + at_chunk;
    const __nv_bfloat16* Bg = B + (size_t)bt_row * N + bx * GBN + bt_chunk;

    uint32_t sA_u32 = (uint32_t)__cvta_generic_to_shared(sA);
    uint32_t sB_u32 = (uint32_t)__cvta_generic_to_shared(sB);

    auto load_tile = [&](int stage, int k0) {
        uint32_t a_dst = sA_u32 + (stage * A_STAGE_ELEMS + at_row * APITCH + at_chunk) * 2;
        cp16(a_dst,                       Ag + k0);
        cp16(a_dst + 64 * APITCH * 2,     Ag + (size_t)64 * K + k0);
        uint32_t b_dst = sB_u32 + (stage * B_STAGE_ELEMS + bt_row * BPITCH + bt_chunk) * 2;
        cp16(b_dst,                       Bg + (size_t)k0 * N);
        cp16(b_dst + 16 * BPITCH * 2,     Bg + (size_t)(k0 + 16) * N);
    };

    float acc[4][4][4];
#pragma unroll
    for (int i = 0; i < 4; i++)
#pragma unroll
        for (int j = 0; j < 4; j++)
#pragma unroll
            for (int r = 0; r < 4; r++) acc[i][j][r] = 0.0f;

    const int KT = K / GBK;

#pragma unroll
    for (int s = 0; s < GSTAGES - 1; s++) { load_tile(s, s * GBK); cp_commit(); }

    // ldmatrix lane-address components (round-7: same map for A and B-trans)
    const int a_lrow = (lane & 15);
    const int a_lcol = (lane >> 4) << 3;

    int st = 0, lt_st = GSTAGES - 1;
    for (int kt = 0; kt < KT; kt++) {
        cp_wait<GSTAGES - 2>();
        __syncthreads();

        uint32_t aBase = sA_u32 + (st * A_STAGE_ELEMS) * 2;
        uint32_t bBase = sB_u32 + (st * B_STAGE_ELEMS) * 2;

#pragma unroll
        for (int ks = 0; ks < 2; ks++) {
            uint32_t a[4][4];
#pragma unroll
            for (int i = 0; i < 4; i++) {
                int row = wm * 64 + i * 16 + a_lrow;
                int col = ks * 16 + a_lcol;
                ldsm_x4(a[i][0], a[i][1], a[i][2], a[i][3],
                        aBase + (row * APITCH + col) * 2);
            }
            uint32_t b[4][2];
#pragma unroll
            for (int j2 = 0; j2 < 2; j2++) {
                // ROUND-7 MAP (restored): rows = k (lane&15), col half by lane>>4
                int row = ks * 16 + a_lrow;
                int col = wn * 32 + j2 * 16 + a_lcol;
                uint32_t r0, r1, r2, r3;
                ldsm_x4_t(r0, r1, r2, r3, bBase + (row * BPITCH + col) * 2);
                b[2 * j2][0] = r0; b[2 * j2][1] = r1;
                b[2 * j2 + 1][0] = r2; b[2 * j2 + 1][1] = r3;
            }
#pragma unroll
            for (int i = 0; i < 4; i++)
#pragma unroll
                for (int j = 0; j < 4; j++)
                    mma16816(acc[i][j][0], acc[i][j][1], acc[i][j][2], acc[i][j][3],
                             a[i][0], a[i][1], a[i][2], a[i][3],
                             b[j][0], b[j][1]);
        }

        __syncthreads();
        int lt = kt + GSTAGES - 1;
        if (lt < KT) load_tile(lt_st, lt * GBK);
        cp_commit();
        if (++st == GSTAGES) st = 0;
        if (++lt_st == GSTAGES) lt_st = 0;
    }

    const int row_base = by * GBM + wm * 64 + (lane >> 2);
    const int col_base = bx * GBN + wn * 32 + (lane & 3) * 2;
#pragma unroll
    for (int i = 0; i < 4; i++) {
#pragma unroll
        for (int j = 0; j < 4; j++) {
            int c = col_base + j * 8;
            float b0 = bias ? bias[c]     : 0.0f;
            float b1 = bias ? bias[c + 1] : 0.0f;
            float* p0 = C + (size_t)(row_base + i * 16) * N + c;
            float* p1 = C + (size_t)(row_base + i * 16 + 8) * N + c;
            p0[0] = acc[i][j][0] + b0; p0[1] = acc[i][j][1] + b1;
            p1[0] = acc[i][j][2] + b0; p1[1] = acc[i][j][3] + b1;
        }
    }
}

// generic (used for the Wo projection, with bias)
__global__ __launch_bounds__(256, 2)
void gemm_bf16_kernel(const __nv_bfloat16* __restrict__ A,
                      const __nv_bfloat16* __restrict__ B,
                      float* __restrict__ C, int M, int N, int K,
                      const float* __restrict__ bias) {
    gemm_body(A, B, C, M, N, K, bias);
}

// fused Q/K/V: blockIdx.z selects weight + output; one launch, 3x the CTAs
__global__ __launch_bounds__(256, 2)
void gemm_qkv_kernel(const __nv_bfloat16* __restrict__ A,
                     const __nv_bfloat16* __restrict__ Bq,
                     const __nv_bfloat16* __restrict__ Bk,
                     const __nv_bfloat16* __restrict__ Bv,
                     float* __restrict__ Cq,
                     float* __restrict__ Ck,
                     float* __restrict__ Cv,
                     int M, int N, int K) {
    const __nv_bfloat16* B = (blockIdx.z == 0) ? Bq : (blockIdx.z == 1) ? Bk : Bv;
    float*               C = (blockIdx.z == 0) ? Cq : (blockIdx.z == 1) ? Ck : Cv;
    gemm_body(A, B, C, M, N, K, nullptr);
}

// ============================================================================
// RoPE
// ============================================================================
__global__ __launch_bounds__(256)
void rope_kernel(float* __restrict__ X, const float* __restrict__ rope,
                 float scale) {
    int i = blockIdx.x * blockDim.x + threadIdx.x;
    int p  = i & 63;
    int h  = (i >> 6) & 15;
    int bn = i >> 10;
    float rr = rope[bn * DH + 2 * p];
    float ri = rope[bn * DH + 2 * p + 1];
    float* base = X + (size_t)bn * DMODEL + h * DH + 2 * p;
    float xr = base[0] * scale;
    float xi = base[1] * scale;
    base[0] = xr * rr - xi * ri;
    base[1] = xr * ri + xi * rr;
}

// ============================================================================
// MMA flash attention, hi/lo split (rounds 4/6/7, verified).
// Epilogue writes O directly as [hi|lo|hi] bf16 rows into g_a.
// ============================================================================
#define AQT   128
#define AKT   64
#define APIT  136
#define AQ_ELEMS  (AQT * APIT)
#define AKV_ELEMS (AKT * APIT)
#define ATT2_SMEM_BYTES ((2 * AQ_ELEMS + 4 * AKV_ELEMS) * 2)   // 139264

__device__ __forceinline__ void split_store4(__nv_bfloat16* hiP,
                                             __nv_bfloat16* loP, float4 v) {
    __nv_bfloat16 h0 = __float2bfloat16(v.x);
    __nv_bfloat16 h1 = __float2bfloat16(v.y);
    __nv_bfloat16 h2 = __float2bfloat16(v.z);
    __nv_bfloat16 h3 = __float2bfloat16(v.w);
    __nv_bfloat16 l0 = __float2bfloat16(v.x - __bfloat162float(h0));
    __nv_bfloat16 l1 = __float2bfloat16(v.y - __bfloat162float(h1));
    __nv_bfloat16 l2 = __float2bfloat16(v.z - __bfloat162float(h2));
    __nv_bfloat16 l3 = __float2bfloat16(v.w - __bfloat162float(h3));
    *(__nv_bfloat162*)(hiP)     = __halves2bfloat162(h0, h1);
    *(__nv_bfloat162*)(hiP + 2) = __halves2bfloat162(h2, h3);
    *(__nv_bfloat162*)(loP)     = __halves2bfloat162(l0, l1);
    *(__nv_bfloat162*)(loP + 2) = __halves2bfloat162(l2, l3);
}

__device__ __forceinline__ void store_split2(__nv_bfloat16* row, int c,
                                             float v0, float v1) {
    __nv_bfloat16 h0 = __float2bfloat16(v0);
    __nv_bfloat16 h1 = __float2bfloat16(v1);
    __nv_bfloat16 l0 = __float2bfloat16(v0 - __bfloat162float(h0));
    __nv_bfloat16 l1 = __float2bfloat16(v1 - __bfloat162float(h1));
    __nv_bfloat162 hp = __halves2bfloat162(h0, h1);
    *(__nv_bfloat162*)(row + c)              = hp;
    *(__nv_bfloat162*)(row + DMODEL + c)     = __halves2bfloat162(l0, l1);
    *(__nv_bfloat162*)(row + 2 * DMODEL + c) = hp;
}

__global__ __launch_bounds__(256, 1)
void attn_mma_kernel(const float* __restrict__ Q, const float* __restrict__ K,
                     const float* __restrict__ V,
                     __nv_bfloat16* __restrict__ Oa) {
    extern __shared__ __nv_bfloat16 smb[];
    __nv_bfloat16* Qhi = smb;
    __nv_bfloat16* Qlo = smb + AQ_ELEMS;
    __nv_bfloat16* Khi = smb + 2 * AQ_ELEMS;
    __nv_bfloat16* Klo = Khi + AKV_ELEMS;
    __nv_bfloat16* Vhi = Klo + AKV_ELEMS;
    __nv_bfloat16* Vlo = Vhi + AKV_ELEMS;

    const int tid  = threadIdx.x;
    const int warp = tid >> 5;
    const int lane = tid & 31;
    const int qt = blockIdx.x;
    const int bh = blockIdx.y;
    const int b  = bh >> 4;
    const int h  = bh & 15;

    const float* Qg = Q + ((size_t)b * SEQ + qt * AQT) * DMODEL + h * DH;
    const float* Kg = K + ((size_t)b * SEQ) * DMODEL + h * DH;
    const float* Vg = V + ((size_t)b * SEQ) * DMODEL + h * DH;
    __nv_bfloat16* Og = Oa + ((size_t)b * SEQ + qt * AQT) * KSPLIT + h * DH;

#pragma unroll
    for (int it = 0; it < 16; it++) {
        int idx = tid + it * 256;
        int r = idx >> 5, c4 = (idx & 31) << 2;
        float4 v = *(const float4*)(Qg + (size_t)r * DMODEL + c4);
        split_store4(Qhi + r * APIT + c4, Qlo + r * APIT + c4, v);
    }

    uint32_t uQhi = (uint32_t)__cvta_generic_to_shared(Qhi);
    uint32_t uQlo = (uint32_t)__cvta_generic_to_shared(Qlo);
    uint32_t uKhi = (uint32_t)__cvta_generic_to_shared(Khi);
    uint32_t uKlo = (uint32_t)__cvta_generic_to_shared(Klo);
    uint32_t uVhi = (uint32_t)__cvta_generic_to_shared(Vhi);
    uint32_t uVlo = (uint32_t)__cvta_generic_to_shared(Vlo);

    const float sscale = 0.08838834764831845f;

    float m0 = -1e30f, m1 = -1e30f, l0 = 0.0f, l1 = 0.0f;
    float oacc[16][4];
#pragma unroll
    for (int nt = 0; nt < 16; nt++)
#pragma unroll
        for (int e = 0; e < 4; e++) oacc[nt][e] = 0.0f;

    const int rowA = lane & 15;
    const int colA = (lane >> 4) << 3;
    const int rowK = (lane & 7) + ((lane >> 4) << 3);
    const int colK = ((lane >> 3) & 1) << 3;
    const int rowV = lane & 15;
    const int colV = (lane >> 4) << 3;

    const uint32_t qhiBase = uQhi + ((warp * 16 + rowA) * APIT) * 2;
    const uint32_t qloBase = uQlo + ((warp * 16 + rowA) * APIT) * 2;

    for (int kt = 0; kt < SEQ / AKT; kt++) {
        __syncthreads();
#pragma unroll
        for (int it = 0; it < 8; it++) {
            int idx = tid + it * 256;
            int r = idx >> 5, c4 = (idx & 31) << 2;
            float4 kv = *(const float4*)(Kg + (size_t)(kt * AKT + r) * DMODEL + c4);
            split_store4(Khi + r * APIT + c4, Klo + r * APIT + c4, kv);
            float4 vv = *(const float4*)(Vg + (size_t)(kt * AKT + r) * DMODEL + c4);
            split_store4(Vhi + r * APIT + c4, Vlo + r * APIT + c4, vv);
        }
        __syncthreads();

        float s[8][4];
#pragma unroll
        for (int nt = 0; nt < 8; nt++)
#pragma unroll
            for (int e = 0; e < 4; e++) s[nt][e] = 0.0f;

#pragma unroll
        for (int ks = 0; ks < 8; ks++) {
            uint32_t ah[4], al[4];
            ldsm_x4(ah[0], ah[1], ah[2], ah[3],
                    qhiBase + (ks * 16 + colA) * 2);
            ldsm_x4(al[0], al[1], al[2], al[3],
                    qloBase + (ks * 16 + colA) * 2);
#pragma unroll
            for (int jn = 0; jn < 4; jn++) {
                uint32_t b0, b1, b2, b3;
                ldsm_x4(b0, b1, b2, b3,
                        uKhi + ((jn * 16 + rowK) * APIT + ks * 16 + colK) * 2);
                mma16816(s[2*jn][0], s[2*jn][1], s[2*jn][2], s[2*jn][3],
                         ah[0], ah[1], ah[2], ah[3], b0, b1);
                mma16816(s[2*jn+1][0], s[2*jn+1][1], s[2*jn+1][2], s[2*jn+1][3],
                         ah[0], ah[1], ah[2], ah[3], b2, b3);
                mma16816(s[2*jn][0], s[2*jn][1], s[2*jn][2], s[2*jn][3],
                         al[0], al[1], al[2], al[3], b0, b1);
                mma16816(s[2*jn+1][0], s[2*jn+1][1], s[2*jn+1][2], s[2*jn+1][3],
                         al[0], al[1], al[2], al[3], b2, b3);
                ldsm_x4(b0, b1, b2, b3,
                        uKlo + ((jn * 16 + rowK) * APIT + ks * 16 + colK) * 2);
                mma16816(s[2*jn][0], s[2*jn][1], s[2*jn][2], s[2*jn][3],
                         ah[0], ah[1], ah[2], ah[3], b0, b1);
                mma16816(s[2*jn+1][0], s[2*jn+1][1], s[2*jn+1][2], s[2*jn+1][3],
                         ah[0], ah[1], ah[2], ah[3], b2, b3);
            }
        }

        float tm0 = -1e30f, tm1 = -1e30f;
#pragma unroll
        for (int nt = 0; nt < 8; nt++) {
            s[nt][0] *= sscale; s[nt][1] *= sscale;
            s[nt][2] *= sscale; s[nt][3] *= sscale;
            tm0 = fmaxf(tm0, fmaxf(s[nt][0], s[nt][1]));
            tm1 = fmaxf(tm1, fmaxf(s[nt][2], s[nt][3]));
        }
        tm0 = fmaxf(tm0, __shfl_xor_sync(0xffffffffu, tm0, 1));
        tm0 = fmaxf(tm0, __shfl_xor_sync(0xffffffffu, tm0, 2));
        tm1 = fmaxf(tm1, __shfl_xor_sync(0xffffffffu, tm1, 1));
        tm1 = fmaxf(tm1, __shfl_xor_sync(0xffffffffu, tm1, 2));

        float mn0 = fmaxf(m0, tm0), mn1 = fmaxf(m1, tm1);
        float al0 = __expf(m0 - mn0), al1 = __expf(m1 - mn1);
        m0 = mn0; m1 = mn1;

        float rs0 = 0.0f, rs1 = 0.0f;
        uint32_t aPhi[4][4], aPlo[4][4];
#pragma unroll
        for (int nt = 0; nt < 8; nt++) {
            float p0 = __expf(s[nt][0] - mn0);
            float p1 = __expf(s[nt][1] - mn0);
            float p2 = __expf(s[nt][2] - mn1);
            float p3 = __expf(s[nt][3] - mn1);
            rs0 += p0 + p1; rs1 += p2 + p3;
            __nv_bfloat16 f0 = __float2bfloat16(p0);
            __nv_bfloat16 f1 = __float2bfloat16(p1);
            __nv_bfloat16 f2 = __float2bfloat16(p2);
            __nv_bfloat16 f3 = __float2bfloat16(p3);
            __nv_bfloat16 g0 = __float2bfloat16(p0 - __bfloat162float(f0));
            __nv_bfloat16 g1 = __float2bfloat16(p1 - __bfloat162float(f1));
            __nv_bfloat16 g2 = __float2bfloat16(p2 - __bfloat162float(f2));
            __nv_bfloat16 g3 = __float2bfloat16(p3 - __bfloat162float(f3));
            int t4 = nt >> 1, hh = (nt & 1) << 1;
            aPhi[t4][hh]     = pack_bf16x2(f0, f1);
            aPhi[t4][hh + 1] = pack_bf16x2(f2, f3);
            aPlo[t4][hh]     = pack_bf16x2(g0, g1);
            aPlo[t4][hh + 1] = pack_bf16x2(g2, g3);
        }
        rs0 += __shfl_xor_sync(0xffffffffu, rs0, 1);
        rs0 += __shfl_xor_sync(0xffffffffu, rs0, 2);
        rs1 += __shfl_xor_sync(0xffffffffu, rs1, 1);
        rs1 += __shfl_xor_sync(0xffffffffu, rs1, 2);
        l0 = l0 * al0 + rs0;
        l1 = l1 * al1 + rs1;

#pragma unroll
        for (int nt = 0; nt < 16; nt++) {
            oacc[nt][0] *= al0; oacc[nt][1] *= al0;
            oacc[nt][2] *= al1; oacc[nt][3] *= al1;
        }

#pragma unroll
        for (int k4 = 0; k4 < 4; k4++) {
#pragma unroll
            for (int jd = 0; jd < 8; jd++) {
                uint32_t b0, b1, b2, b3;
                ldsm_x4_t(b0, b1, b2, b3,
                          uVhi + ((k4 * 16 + rowV) * APIT + jd * 16 + colV) * 2);
                mma16816(oacc[2*jd][0], oacc[2*jd][1], oacc[2*jd][2], oacc[2*jd][3],
                         aPhi[k4][0], aPhi[k4][1], aPhi[k4][2], aPhi[k4][3], b0, b1);
                mma16816(oacc[2*jd+1][0], oacc[2*jd+1][1], oacc[2*jd+1][2], oacc[2*jd+1][3],
                         aPhi[k4][0], aPhi[k4][1], aPhi[k4][2], aPhi[k4][3], b2, b3);
                mma16816(oacc[2*jd][0], oacc[2*jd][1], oacc[2*jd][2], oacc[2*jd][3],
                         aPlo[k4][0], aPlo[k4][1], aPlo[k4][2], aPlo[k4][3], b0, b1);
                mma16816(oacc[2*jd+1][0], oacc[2*jd+1][1], oacc[2*jd+1][2], oacc[2*jd+1][3],
                         aPlo[k4][0], aPlo[k4][1], aPlo[k4][2], aPlo[k4][3], b2, b3);
                ldsm_x4_t(b0, b1, b2, b3,
                          uVlo + ((k4 * 16 + rowV) * APIT + jd * 16 + colV) * 2);
                mma16816(oacc[2*jd][0], oacc[2*jd][1], oacc[2*jd][2], oacc[2*jd][3],
                         aPhi[k4][0], aPhi[k4][1], aPhi[k4][2], aPhi[k4][3], b0, b1);
                mma16816(oacc[2*jd+1][0], oacc[2*jd+1][1], oacc[2*jd+1][2], oacc[2*jd+1][3],
                         aPhi[k4][0], aPhi[k4][1], aPhi[k4][2], aPhi[k4][3], b2, b3);
            }
        }
    }

    // ---- normalize + write split [hi|lo|hi] rows of g_a ----
    float inv0 = 1.0f / l0, inv1 = 1.0f / l1;
    int row0 = warp * 16 + (lane >> 2);
    int c0 = (lane & 3) * 2;
#pragma unroll
    for (int nt = 0; nt < 16; nt++) {
        __nv_bfloat16* r0p = Og + (size_t)row0 * KSPLIT;
        __nv_bfloat16* r1p = Og + (size_t)(row0 + 8) * KSPLIT;
        store_split2(r0p, nt * 8 + c0, oacc[nt][0] * inv0, oacc[nt][1] * inv0);
        store_split2(r1p, nt * 8 + c0, oacc[nt][2] * inv1, oacc[nt][3] * inv1);
    }
}

// ============================================================================
// host
// ============================================================================
extern "C" void kernel_launch(void* const* d_in, const int* in_sizes, int n_in,
                              void* d_out, int out_size) {
    const float* x   = (const float*)d_in[0];
    const float* qr  = (const float*)d_in[1];
    const float* kr  = (const float*)d_in[2];
    const float* Wq  = (const float*)d_in[3];
    const float* Wk  = (const float*)d_in[4];
    const float* Wv  = (const float*)d_in[5];
    const float* Wo  = (const float*)d_in[6];
    const float* bo  = (const float*)d_in[7];
    float* out = (float*)d_out;

    void *pq, *pk, *pv, *pab, *pwq, *pwk, *pwv, *pwo;
    cudaGetSymbolAddress(&pq,  g_q);
    cudaGetSymbolAddress(&pk,  g_k);
    cudaGetSymbolAddress(&pv,  g_v);
    cudaGetSymbolAddress(&pab, g_a);
    cudaGetSymbolAddress(&pwq, g_wq);
    cudaGetSymbolAddress(&pwk, g_wk);
    cudaGetSymbolAddress(&pwv, g_wv);
    cudaGetSymbolAddress(&pwo, g_wo);

    cudaFuncSetAttribute(gemm_bf16_kernel,
                         cudaFuncAttributeMaxDynamicSharedMemorySize,
                         GEMM_SMEM_BYTES);
    cudaFuncSetAttribute(gemm_qkv_kernel,
                         cudaFuncAttributeMaxDynamicSharedMemorySize,
                         GEMM_SMEM_BYTES);
    cudaFuncSetAttribute(attn_mma_kernel,
                         cudaFuncAttributeMaxDynamicSharedMemorySize,
                         ATT2_SMEM_BYTES);

    int wElems = DMODEL * DMODEL;
    split_b_kernel<<<(wElems + 255) / 256, 256>>>(Wq, (__nv_bfloat16*)pwq);
    split_b_kernel<<<(wElems + 255) / 256, 256>>>(Wk, (__nv_bfloat16*)pwk);
    split_b_kernel<<<(wElems + 255) / 256, 256>>>(Wv, (__nv_bfloat16*)pwv);
    split_b_kernel<<<(wElems + 255) / 256, 256>>>(Wo, (__nv_bfloat16*)pwo);

    int aElems = ROWS * DMODEL;
    split_a_kernel<<<(aElems + 255) / 256, 256>>>(x, (__nv_bfloat16*)pab);

    // fused Q/K/V projection: one launch, 3x CTAs -> better wave packing
    dim3 qkv_grid(DMODEL / GBN, ROWS / GBM, 3);   // (16, 32, 3) = 1536 CTAs
    gemm_qkv_kernel<<<qkv_grid, 256, GEMM_SMEM_BYTES>>>(
        (const __nv_bfloat16*)pab,
        (const __nv_bfloat16*)pwq, (const __nv_bfloat16*)pwk,
        (const __nv_bfloat16*)pwv,
        (float*)pq, (float*)pk, (float*)pv,
        ROWS, DMODEL, KSPLIT);

    int rope_pairs = BATCH * SEQ * HEADS * (DH / 2);
    rope_kernel<<<rope_pairs / 256, 256>>>((float*)pq, qr, 0.08838834764831845f);
    rope_kernel<<<rope_pairs / 256, 256>>>((float*)pk, kr, 1.0f);

    attn_mma_kernel<<<dim3(SEQ / AQT, BATCH * HEADS), 256, ATT2_SMEM_BYTES>>>(
        (const float*)pq, (const float*)pk, (const float*)pv,
        (__nv_bfloat16*)pab);

    gemm_bf16_kernel<<<dim3(DMODEL / GBN, ROWS / GBM), 256, GEMM_SMEM_BYTES>>>(
        (const __nv_bfloat16*)pab, (const __nv_bfloat16*)pwo, out,
        ROWS, DMODEL, KSPLIT, bo);
}

// round 12
// speedup vs baseline: 2.7929x; 1.0697x over previous
#include <cuda_runtime.h>
#include <cuda_bf16.h>
#include <cstdint>

// ============================================================================
// AttentionWithRoPE — round 12: BK=64 single-sync GEMM pipeline (re-introduced
// in isolation, now with the CORRECT round-7 B-fragment ldmatrix map).
// Everything else identical to round 11 (2251us, rel_err 1.884721e-05).
//   B=2, N=2048, D=2048, H=16, Dh=128
// ============================================================================

#define BATCH   2
#define SEQ     2048
#define DMODEL  2048
#define HEADS   16
#define DH      128
#define ROWS    (BATCH * SEQ)          // 4096
#define KSPLIT  (3 * DMODEL)           // 6144

// ---- scratch (static __device__, no allocations; 16B-aligned) ----
__device__ __align__(16) float g_q[ROWS * DMODEL];
__device__ __align__(16) float g_k[ROWS * DMODEL];
__device__ __align__(16) float g_v[ROWS * DMODEL];
__device__ __align__(16) __nv_bfloat16 g_a  [ROWS * KSPLIT];
__device__ __align__(16) __nv_bfloat16 g_wq [KSPLIT * DMODEL];
__device__ __align__(16) __nv_bfloat16 g_wk [KSPLIT * DMODEL];
__device__ __align__(16) __nv_bfloat16 g_wv [KSPLIT * DMODEL];
__device__ __align__(16) __nv_bfloat16 g_wo [KSPLIT * DMODEL];

// ============================================================================
// common MMA / ldmatrix helpers
// ============================================================================
__device__ __forceinline__ void cp16(uint32_t smem_addr, const void* gptr) {
    asm volatile("cp.async.cg.shared.global [%0], [%1], 16;"
                 :: "r"(smem_addr), "l"(gptr));
}
__device__ __forceinline__ void cp_commit() {
    asm volatile("cp.async.commit_group;");
}
template <int Nwait>
__device__ __forceinline__ void cp_wait() {
    asm volatile("cp.async.wait_group %0;" :: "n"(Nwait));
}
__device__ __forceinline__ void ldsm_x4(uint32_t& r0, uint32_t& r1,
                                        uint32_t& r2, uint32_t& r3,
                                        uint32_t addr) {
    asm volatile("ldmatrix.sync.aligned.m8n8.x4.shared.b16 {%0,%1,%2,%3}, [%4];"
                 : "=r"(r0), "=r"(r1), "=r"(r2), "=r"(r3) : "r"(addr));
}
__device__ __forceinline__ void ldsm_x4_t(uint32_t& r0, uint32_t& r1,
                                          uint32_t& r2, uint32_t& r3,
                                          uint32_t addr) {
    asm volatile("ldmatrix.sync.aligned.m8n8.x4.trans.shared.b16 {%0,%1,%2,%3}, [%4];"
                 : "=r"(r0), "=r"(r1), "=r"(r2), "=r"(r3) : "r"(addr));
}
__device__ __forceinline__ void mma16816(float& c0, float& c1, float& c2, float& c3,
                                         uint32_t a0, uint32_t a1, uint32_t a2,
                                         uint32_t a3, uint32_t b0, uint32_t b1) {
    asm volatile(
        "mma.sync.aligned.m16n8k16.row.col.f32.bf16.bf16.f32 "
        "{%0,%1,%2,%3}, {%4,%5,%6,%7}, {%8,%9}, {%0,%1,%2,%3};"
        : "+f"(c0), "+f"(c1), "+f"(c2), "+f"(c3)
        : "r"(a0), "r"(a1), "r"(a2), "r"(a3), "r"(b0), "r"(b1));
}
__device__ __forceinline__ uint32_t pack_bf16x2(__nv_bfloat16 lo, __nv_bfloat16 hi) {
    __nv_bfloat162 p = __halves2bfloat162(lo, hi);
    return *reinterpret_cast<uint32_t*>(&p);
}

// ============================================================================
// hi/lo split kernels — SCALAR (verified)
// ============================================================================
__global__ __launch_bounds__(256)
void split_a_kernel(const float* __restrict__ X, __nv_bfloat16* __restrict__ A) {
    int i = blockIdx.x * blockDim.x + threadIdx.x;
    if (i >= ROWS * DMODEL) return;
    int r = i / DMODEL, c = i % DMODEL;
    float x = X[i];
    __nv_bfloat16 hi = __float2bfloat16(x);
    __nv_bfloat16 lo = __float2bfloat16(x - __bfloat162float(hi));
    __nv_bfloat16* row = A + (size_t)r * KSPLIT;
    row[c]              = hi;
    row[DMODEL + c]     = lo;
    row[2 * DMODEL + c] = hi;
}
__global__ __launch_bounds__(256)
void split_b_kernel(const float* __restrict__ W, __nv_bfloat16* __restrict__ Bo) {
    int i = blockIdx.x * blockDim.x + threadIdx.x;
    if (i >= DMODEL * DMODEL) return;
    float w = W[i];
    __nv_bfloat16 hi = __float2bfloat16(w);
    __nv_bfloat16 lo = __float2bfloat16(w - __bfloat162float(hi));
    Bo[i]                                 = hi;
    Bo[(size_t)DMODEL * DMODEL + i]       = hi;
    Bo[(size_t)2 * DMODEL * DMODEL + i]   = lo;
}

// ============================================================================
// bf16 tensor-core GEMM body: BM=BN=128, BK=64, 256 threads, 3-stage
// cp.async, SINGLE-sync pipeline, 2 CTAs/SM. Correct round-7 fragment maps.
// ============================================================================
#define GBM 128
#define GBN 128
#define GBK 64
#define GSTAGES 3
#define APITCH 72            // 144B rows (9x16B, odd mod 8 -> conflict-free)
#define BPITCH 136           // 272B rows
#define A_STAGE_ELEMS (GBM * APITCH)   // 9216
#define B_STAGE_ELEMS (GBK * BPITCH)   // 8704
#define GEMM_SMEM_BYTES (GSTAGES * (A_STAGE_ELEMS + B_STAGE_ELEMS) * 2)  // 107520

__device__ __forceinline__ void gemm_body(const __nv_bfloat16* __restrict__ A,
                                          const __nv_bfloat16* __restrict__ B,
                                          float* __restrict__ C,
                                          int M, int N, int K,
                                          const float* __restrict__ bias) {
    extern __shared__ __nv_bfloat16 sm[];
    __nv_bfloat16* sA = sm;
    __nv_bfloat16* sB = sm + GSTAGES * A_STAGE_ELEMS;

    const int tid  = threadIdx.x;
    const int warp = tid >> 5;
    const int lane = tid & 31;
    const int wm = warp >> 2;
    const int wn = warp & 3;
    const int bx = blockIdx.x;
    const int by = blockIdx.y;

    // global load mapping (BK=64): A 128x64, B 64x128; 8 cp16/thread/tile
    const int at_row   = tid >> 3;          // 0..31
    const int at_chunk = (tid & 7) << 3;    // 0..56
    const int bt_row   = tid >> 4;          // 0..15
    const int bt_chunk = (tid & 15) << 3;   // 0..120

    const __nv_bfloat16* Ag = A + (size_t)(by * GBM + at_row) * K + at_chunk;
    const __nv_bfloat16* Bg = B + (size_t)bt_row * N + bx * GBN + bt_chunk;

    uint32_t sA_u32 = (uint32_t)__cvta_generic_to_shared(sA);
    uint32_t sB_u32 = (uint32_t)__cvta_generic_to_shared(sB);

    auto load_tile = [&](int stage, int k0) {
        uint32_t a_dst = sA_u32 + (stage * A_STAGE_ELEMS + at_row * APITCH + at_chunk) * 2;
#pragma unroll
        for (int b = 0; b < 4; b++)
            cp16(a_dst + b * 32 * APITCH * 2, Ag + (size_t)(32 * b) * K + k0);
        uint32_t b_dst = sB_u32 + (stage * B_STAGE_ELEMS + bt_row * BPITCH + bt_chunk) * 2;
#pragma unroll
        for (int b = 0; b < 4; b++)
            cp16(b_dst + b * 16 * BPITCH * 2, Bg + (size_t)(k0 + 16 * b) * N);
    };

    float acc[4][4][4];
#pragma unroll
    for (int i = 0; i < 4; i++)
#pragma unroll
        for (int j = 0; j < 4; j++)
#pragma unroll
            for (int r = 0; r < 4; r++) acc[i][j][r] = 0.0f;

    const int KT = K / GBK;   // 96

    load_tile(0, 0);        cp_commit();
    load_tile(1, GBK);      cp_commit();

    // ldmatrix lane-address components (round-7 verified map, A and B-trans)
    const int a_lrow = (lane & 15);
    const int a_lcol = (lane >> 4) << 3;

    int st = 0, wst = 2;
    for (int kt = 0; kt < KT; kt++) {
        cp_wait<1>();
        __syncthreads();    // stage st visible; prior readers of wst done

        if (kt + 2 < KT) load_tile(wst, (kt + 2) * GBK);
        cp_commit();        // one group per iteration (possibly empty)

        uint32_t aBase = sA_u32 + (st * A_STAGE_ELEMS) * 2;
        uint32_t bBase = sB_u32 + (st * B_STAGE_ELEMS) * 2;

#pragma unroll
        for (int ks = 0; ks < 4; ks++) {
            uint32_t a[4][4];
#pragma unroll
            for (int i = 0; i < 4; i++) {
                int row = wm * 64 + i * 16 + a_lrow;
                int col = ks * 16 + a_lcol;
                ldsm_x4(a[i][0], a[i][1], a[i][2], a[i][3],
                        aBase + (row * APITCH + col) * 2);
            }
            uint32_t b[4][2];
#pragma unroll
            for (int j2 = 0; j2 < 2; j2++) {
                // CORRECT (round-7) trans-B map
                int row = ks * 16 + a_lrow;
                int col = wn * 32 + j2 * 16 + a_lcol;
                uint32_t r0, r1, r2, r3;
                ldsm_x4_t(r0, r1, r2, r3, bBase + (row * BPITCH + col) * 2);
                b[2 * j2][0] = r0; b[2 * j2][1] = r1;
                b[2 * j2 + 1][0] = r2; b[2 * j2 + 1][1] = r3;
            }
#pragma unroll
            for (int i = 0; i < 4; i++)
#pragma unroll
                for (int j = 0; j < 4; j++)
                    mma16816(acc[i][j][0], acc[i][j][1], acc[i][j][2], acc[i][j][3],
                             a[i][0], a[i][1], a[i][2], a[i][3],
                             b[j][0], b[j][1]);
        }

        if (++st == GSTAGES) st = 0;
        if (++wst == GSTAGES) wst = 0;
    }

    const int row_base = by * GBM + wm * 64 + (lane >> 2);
    const int col_base = bx * GBN + wn * 32 + (lane & 3) * 2;
#pragma unroll
    for (int i = 0; i < 4; i++) {
#pragma unroll
        for (int j = 0; j < 4; j++) {
            int c = col_base + j * 8;
            float b0 = bias ? bias[c]     : 0.0f;
            float b1 = bias ? bias[c + 1] : 0.0f;
            float* p0 = C + (size_t)(row_base + i * 16) * N + c;
            float* p1 = C + (size_t)(row_base + i * 16 + 8) * N + c;
            p0[0] = acc[i][j][0] + b0; p0[1] = acc[i][j][1] + b1;
            p1[0] = acc[i][j][2] + b0; p1[1] = acc[i][j][3] + b1;
        }
    }
}

// generic (used for the Wo projection, with bias)
__global__ __launch_bounds__(256, 2)
void gemm_bf16_kernel(const __nv_bfloat16* __restrict__ A,
                      const __nv_bfloat16* __restrict__ B,
                      float* __restrict__ C, int M, int N, int K,
                      const float* __restrict__ bias) {
    gemm_body(A, B, C, M, N, K, bias);
}

// fused Q/K/V: blockIdx.z selects weight + output
__global__ __launch_bounds__(256, 2)
void gemm_qkv_kernel(const __nv_bfloat16* __restrict__ A,
                     const __nv_bfloat16* __restrict__ Bq,
                     const __nv_bfloat16* __restrict__ Bk,
                     const __nv_bfloat16* __restrict__ Bv,
                     float* __restrict__ Cq,
                     float* __restrict__ Ck,
                     float* __restrict__ Cv,
                     int M, int N, int K) {
    const __nv_bfloat16* B = (blockIdx.z == 0) ? Bq : (blockIdx.z == 1) ? Bk : Bv;
    float*               C = (blockIdx.z == 0) ? Cq : (blockIdx.z == 1) ? Ck : Cv;
    gemm_body(A, B, C, M, N, K, nullptr);
}

// ============================================================================
// RoPE
// ============================================================================
__global__ __launch_bounds__(256)
void rope_kernel(float* __restrict__ X, const float* __restrict__ rope,
                 float scale) {
    int i = blockIdx.x * blockDim.x + threadIdx.x;
    int p  = i & 63;
    int h  = (i >> 6) & 15;
    int bn = i >> 10;
    float rr = rope[bn * DH + 2 * p];
    float ri = rope[bn * DH + 2 * p + 1];
    float* base = X + (size_t)bn * DMODEL + h * DH + 2 * p;
    float xr = base[0] * scale;
    float xi = base[1] * scale;
    base[0] = xr * rr - xi * ri;
    base[1] = xr * ri + xi * rr;
}

// ============================================================================
// MMA flash attention, hi/lo split (verified). Epilogue writes [hi|lo|hi].
// ============================================================================
#define AQT   128
#define AKT   64
#define APIT  136
#define AQ_ELEMS  (AQT * APIT)
#define AKV_ELEMS (AKT * APIT)
#define ATT2_SMEM_BYTES ((2 * AQ_ELEMS + 4 * AKV_ELEMS) * 2)   // 139264

__device__ __forceinline__ void split_store4(__nv_bfloat16* hiP,
                                             __nv_bfloat16* loP, float4 v) {
    __nv_bfloat16 h0 = __float2bfloat16(v.x);
    __nv_bfloat16 h1 = __float2bfloat16(v.y);
    __nv_bfloat16 h2 = __float2bfloat16(v.z);
    __nv_bfloat16 h3 = __float2bfloat16(v.w);
    __nv_bfloat16 l0 = __float2bfloat16(v.x - __bfloat162float(h0));
    __nv_bfloat16 l1 = __float2bfloat16(v.y - __bfloat162float(h1));
    __nv_bfloat16 l2 = __float2bfloat16(v.z - __bfloat162float(h2));
    __nv_bfloat16 l3 = __float2bfloat16(v.w - __bfloat162float(h3));
    *(__nv_bfloat162*)(hiP)     = __halves2bfloat162(h0, h1);
    *(__nv_bfloat162*)(hiP + 2) = __halves2bfloat162(h2, h3);
    *(__nv_bfloat162*)(loP)     = __halves2bfloat162(l0, l1);
    *(__nv_bfloat162*)(loP + 2) = __halves2bfloat162(l2, l3);
}

__device__ __forceinline__ void store_split2(__nv_bfloat16* row, int c,
                                             float v0, float v1) {
    __nv_bfloat16 h0 = __float2bfloat16(v0);
    __nv_bfloat16 h1 = __float2bfloat16(v1);
    __nv_bfloat16 l0 = __float2bfloat16(v0 - __bfloat162float(h0));
    __nv_bfloat16 l1 = __float2bfloat16(v1 - __bfloat162float(h1));
    __nv_bfloat162 hp = __halves2bfloat162(h0, h1);
    *(__nv_bfloat162*)(row + c)              = hp;
    *(__nv_bfloat162*)(row + DMODEL + c)     = __halves2bfloat162(l0, l1);
    *(__nv_bfloat162*)(row + 2 * DMODEL + c) = hp;
}

__global__ __launch_bounds__(256, 1)
void attn_mma_kernel(const float* __restrict__ Q, const float* __restrict__ K,
                     const float* __restrict__ V,
                     __nv_bfloat16* __restrict__ Oa) {
    extern __shared__ __nv_bfloat16 smb[];
    __nv_bfloat16* Qhi = smb;
    __nv_bfloat16* Qlo = smb + AQ_ELEMS;
    __nv_bfloat16* Khi = smb + 2 * AQ_ELEMS;
    __nv_bfloat16* Klo = Khi + AKV_ELEMS;
    __nv_bfloat16* Vhi = Klo + AKV_ELEMS;
    __nv_bfloat16* Vlo = Vhi + AKV_ELEMS;

    const int tid  = threadIdx.x;
    const int warp = tid >> 5;
    const int lane = tid & 31;
    const int qt = blockIdx.x;
    const int bh = blockIdx.y;
    const int b  = bh >> 4;
    const int h  = bh & 15;

    const float* Qg = Q + ((size_t)b * SEQ + qt * AQT) * DMODEL + h * DH;
    const float* Kg = K + ((size_t)b * SEQ) * DMODEL + h * DH;
    const float* Vg = V + ((size_t)b * SEQ) * DMODEL + h * DH;
    __nv_bfloat16* Og = Oa + ((size_t)b * SEQ + qt * AQT) * KSPLIT + h * DH;

#pragma unroll
    for (int it = 0; it < 16; it++) {
        int idx = tid + it * 256;
        int r = idx >> 5, c4 = (idx & 31) << 2;
        float4 v = *(const float4*)(Qg + (size_t)r * DMODEL + c4);
        split_store4(Qhi + r * APIT + c4, Qlo + r * APIT + c4, v);
    }

    uint32_t uQhi = (uint32_t)__cvta_generic_to_shared(Qhi);
    uint32_t uQlo = (uint32_t)__cvta_generic_to_shared(Qlo);
    uint32_t uKhi = (uint32_t)__cvta_generic_to_shared(Khi);
    uint32_t uKlo = (uint32_t)__cvta_generic_to_shared(Klo);
    uint32_t uVhi = (uint32_t)__cvta_generic_to_shared(Vhi);
    uint32_t uVlo = (uint32_t)__cvta_generic_to_shared(Vlo);

    const float sscale = 0.08838834764831845f;

    float m0 = -1e30f, m1 = -1e30f, l0 = 0.0f, l1 = 0.0f;
    float oacc[16][4];
#pragma unroll
    for (int nt = 0; nt < 16; nt++)
#pragma unroll
        for (int e = 0; e < 4; e++) oacc[nt][e] = 0.0f;

    const int rowA = lane & 15;
    const int colA = (lane >> 4) << 3;
    const int rowK = (lane & 7) + ((lane >> 4) << 3);
    const int colK = ((lane >> 3) & 1) << 3;
    const int rowV = lane & 15;
    const int colV = (lane >> 4) << 3;

    const uint32_t qhiBase = uQhi + ((warp * 16 + rowA) * APIT) * 2;
    const uint32_t qloBase = uQlo + ((warp * 16 + rowA) * APIT) * 2;

    for (int kt = 0; kt < SEQ / AKT; kt++) {
        __syncthreads();
#pragma unroll
        for (int it = 0; it < 8; it++) {
            int idx = tid + it * 256;
            int r = idx >> 5, c4 = (idx & 31) << 2;
            float4 kv = *(const float4*)(Kg + (size_t)(kt * AKT + r) * DMODEL + c4);
            split_store4(Khi + r * APIT + c4, Klo + r * APIT + c4, kv);
            float4 vv = *(const float4*)(Vg + (size_t)(kt * AKT + r) * DMODEL + c4);
            split_store4(Vhi + r * APIT + c4, Vlo + r * APIT + c4, vv);
        }
        __syncthreads();

        float s[8][4];
#pragma unroll
        for (int nt = 0; nt < 8; nt++)
#pragma unroll
            for (int e = 0; e < 4; e++) s[nt][e] = 0.0f;

#pragma unroll
        for (int ks = 0; ks < 8; ks++) {
            uint32_t ah[4], al[4];
            ldsm_x4(ah[0], ah[1], ah[2], ah[3],
                    qhiBase + (ks * 16 + colA) * 2);
            ldsm_x4(al[0], al[1], al[2], al[3],
                    qloBase + (ks * 16 + colA) * 2);
#pragma unroll
            for (int jn = 0; jn < 4; jn++) {
                uint32_t b0, b1, b2, b3;
                ldsm_x4(b0, b1, b2, b3,
                        uKhi + ((jn * 16 + rowK) * APIT + ks * 16 + colK) * 2);
                mma16816(s[2*jn][0], s[2*jn][1], s[2*jn][2], s[2*jn][3],
                         ah[0], ah[1], ah[2], ah[3], b0, b1);
                mma16816(s[2*jn+1][0], s[2*jn+1][1], s[2*jn+1][2], s[2*jn+1][3],
                         ah[0], ah[1], ah[2], ah[3], b2, b3);
                mma16816(s[2*jn][0], s[2*jn][1], s[2*jn][2], s[2*jn][3],
                         al[0], al[1], al[2], al[3], b0, b1);
                mma16816(s[2*jn+1][0], s[2*jn+1][1], s[2*jn+1][2], s[2*jn+1][3],
                         al[0], al[1], al[2], al[3], b2, b3);
                ldsm_x4(b0, b1, b2, b3,
                        uKlo + ((jn * 16 + rowK) * APIT + ks * 16 + colK) * 2);
                mma16816(s[2*jn][0], s[2*jn][1], s[2*jn][2], s[2*jn][3],
                         ah[0], ah[1], ah[2], ah[3], b0, b1);
                mma16816(s[2*jn+1][0], s[2*jn+1][1], s[2*jn+1][2], s[2*jn+1][3],
                         ah[0], ah[1], ah[2], ah[3], b2, b3);
            }
        }

        float tm0 = -1e30f, tm1 = -1e30f;
#pragma unroll
        for (int nt = 0; nt < 8; nt++) {
            s[nt][0] *= sscale; s[nt][1] *= sscale;
            s[nt][2] *= sscale; s[nt][3] *= sscale;
            tm0 = fmaxf(tm0, fmaxf(s[nt][0], s[nt][1]));
            tm1 = fmaxf(tm1, fmaxf(s[nt][2], s[nt][3]));
        }
        tm0 = fmaxf(tm0, __shfl_xor_sync(0xffffffffu, tm0, 1));
        tm0 = fmaxf(tm0, __shfl_xor_sync(0xffffffffu, tm0, 2));
        tm1 = fmaxf(tm1, __shfl_xor_sync(0xffffffffu, tm1, 1));
        tm1 = fmaxf(tm1, __shfl_xor_sync(0xffffffffu, tm1, 2));

        float mn0 = fmaxf(m0, tm0), mn1 = fmaxf(m1, tm1);
        float al0 = __expf(m0 - mn0), al1 = __expf(m1 - mn1);
        m0 = mn0; m1 = mn1;

        float rs0 = 0.0f, rs1 = 0.0f;
        uint32_t aPhi[4][4], aPlo[4][4];
#pragma unroll
        for (int nt = 0; nt < 8; nt++) {
            float p0 = __expf(s[nt][0] - mn0);
            float p1 = __expf(s[nt][1] - mn0);
            float p2 = __expf(s[nt][2] - mn1);
            float p3 = __expf(s[nt][3] - mn1);
            rs0 += p0 + p1; rs1 += p2 + p3;
            __nv_bfloat16 f0 = __float2bfloat16(p0);
            __nv_bfloat16 f1 = __float2bfloat16(p1);
            __nv_bfloat16 f2 = __float2bfloat16(p2);
            __nv_bfloat16 f3 = __float2bfloat16(p3);
            __nv_bfloat16 g0 = __float2bfloat16(p0 - __bfloat162float(f0));
            __nv_bfloat16 g1 = __float2bfloat16(p1 - __bfloat162float(f1));
            __nv_bfloat16 g2 = __float2bfloat16(p2 - __bfloat162float(f2));
            __nv_bfloat16 g3 = __float2bfloat16(p3 - __bfloat162float(f3));
            int t4 = nt >> 1, hh = (nt & 1) << 1;
            aPhi[t4][hh]     = pack_bf16x2(f0, f1);
            aPhi[t4][hh + 1] = pack_bf16x2(f2, f3);
            aPlo[t4][hh]     = pack_bf16x2(g0, g1);
            aPlo[t4][hh + 1] = pack_bf16x2(g2, g3);
        }
        rs0 += __shfl_xor_sync(0xffffffffu, rs0, 1);
        rs0 += __shfl_xor_sync(0xffffffffu, rs0, 2);
        rs1 += __shfl_xor_sync(0xffffffffu, rs1, 1);
        rs1 += __shfl_xor_sync(0xffffffffu, rs1, 2);
        l0 = l0 * al0 + rs0;
        l1 = l1 * al1 + rs1;

#pragma unroll
        for (int nt = 0; nt < 16; nt++) {
            oacc[nt][0] *= al0; oacc[nt][1] *= al0;
            oacc[nt][2] *= al1; oacc[nt][3] *= al1;
        }

#pragma unroll
        for (int k4 = 0; k4 < 4; k4++) {
#pragma unroll
            for (int jd = 0; jd < 8; jd++) {
                uint32_t b0, b1, b2, b3;
                ldsm_x4_t(b0, b1, b2, b3,
                          uVhi + ((k4 * 16 + rowV) * APIT + jd * 16 + colV) * 2);
                mma16816(oacc[2*jd][0], oacc[2*jd][1], oacc[2*jd][2], oacc[2*jd][3],
                         aPhi[k4][0], aPhi[k4][1], aPhi[k4][2], aPhi[k4][3], b0, b1);
                mma16816(oacc[2*jd+1][0], oacc[2*jd+1][1], oacc[2*jd+1][2], oacc[2*jd+1][3],
                         aPhi[k4][0], aPhi[k4][1], aPhi[k4][2], aPhi[k4][3], b2, b3);
                mma16816(oacc[2*jd][0], oacc[2*jd][1], oacc[2*jd][2], oacc[2*jd][3],
                         aPlo[k4][0], aPlo[k4][1], aPlo[k4][2], aPlo[k4][3], b0, b1);
                mma16816(oacc[2*jd+1][0], oacc[2*jd+1][1], oacc[2*jd+1][2], oacc[2*jd+1][3],
                         aPlo[k4][0], aPlo[k4][1], aPlo[k4][2], aPlo[k4][3], b2, b3);
                ldsm_x4_t(b0, b1, b2, b3,
                          uVlo + ((k4 * 16 + rowV) * APIT + jd * 16 + colV) * 2);
                mma16816(oacc[2*jd][0], oacc[2*jd][1], oacc[2*jd][2], oacc[2*jd][3],
                         aPhi[k4][0], aPhi[k4][1], aPhi[k4][2], aPhi[k4][3], b0, b1);
                mma16816(oacc[2*jd+1][0], oacc[2*jd+1][1], oacc[2*jd+1][2], oacc[2*jd+1][3],
                         aPhi[k4][0], aPhi[k4][1], aPhi[k4][2], aPhi[k4][3], b2, b3);
            }
        }
    }

    // ---- normalize + write split [hi|lo|hi] rows of g_a ----
    float inv0 = 1.0f / l0, inv1 = 1.0f / l1;
    int row0 = warp * 16 + (lane >> 2);
    int c0 = (lane & 3) * 2;
#pragma unroll
    for (int nt = 0; nt < 16; nt++) {
        __nv_bfloat16* r0p = Og + (size_t)row0 * KSPLIT;
        __nv_bfloat16* r1p = Og + (size_t)(row0 + 8) * KSPLIT;
        store_split2(r0p, nt * 8 + c0, oacc[nt][0] * inv0, oacc[nt][1] * inv0);
        store_split2(r1p, nt * 8 + c0, oacc[nt][2] * inv1, oacc[nt][3] * inv1);
    }
}

// ============================================================================
// host
// ============================================================================
extern "C" void kernel_launch(void* const* d_in, const int* in_sizes, int n_in,
                              void* d_out, int out_size) {
    const float* x   = (const float*)d_in[0];
    const float* qr  = (const float*)d_in[1];
    const float* kr  = (const float*)d_in[2];
    const float* Wq  = (const float*)d_in[3];
    const float* Wk  = (const float*)d_in[4];
    const float* Wv  = (const float*)d_in[5];
    const float* Wo  = (const float*)d_in[6];
    const float* bo  = (const float*)d_in[7];
    float* out = (float*)d_out;

    void *pq, *pk, *pv, *pab, *pwq, *pwk, *pwv, *pwo;
    cudaGetSymbolAddress(&pq,  g_q);
    cudaGetSymbolAddress(&pk,  g_k);
    cudaGetSymbolAddress(&pv,  g_v);
    cudaGetSymbolAddress(&pab, g_a);
    cudaGetSymbolAddress(&pwq, g_wq);
    cudaGetSymbolAddress(&pwk, g_wk);
    cudaGetSymbolAddress(&pwv, g_wv);
    cudaGetSymbolAddress(&pwo, g_wo);

    cudaFuncSetAttribute(gemm_bf16_kernel,
                         cudaFuncAttributeMaxDynamicSharedMemorySize,
                         GEMM_SMEM_BYTES);
    cudaFuncSetAttribute(gemm_qkv_kernel,
                         cudaFuncAttributeMaxDynamicSharedMemorySize,
                         GEMM_SMEM_BYTES);
    cudaFuncSetAttribute(attn_mma_kernel,
                         cudaFuncAttributeMaxDynamicSharedMemorySize,
                         ATT2_SMEM_BYTES);

    int wElems = DMODEL * DMODEL;
    split_b_kernel<<<(wElems + 255) / 256, 256>>>(Wq, (__nv_bfloat16*)pwq);
    split_b_kernel<<<(wElems + 255) / 256, 256>>>(Wk, (__nv_bfloat16*)pwk);
    split_b_kernel<<<(wElems + 255) / 256, 256>>>(Wv, (__nv_bfloat16*)pwv);
    split_b_kernel<<<(wElems + 255) / 256, 256>>>(Wo, (__nv_bfloat16*)pwo);

    int aElems = ROWS * DMODEL;
    split_a_kernel<<<(aElems + 255) / 256, 256>>>(x, (__nv_bfloat16*)pab);

    // fused Q/K/V projection: one launch, 3x CTAs -> better wave packing
    dim3 qkv_grid(DMODEL / GBN, ROWS / GBM, 3);   // (16, 32, 3) = 1536 CTAs
    gemm_qkv_kernel<<<qkv_grid, 256, GEMM_SMEM_BYTES>>>(
        (const __nv_bfloat16*)pab,
        (const __nv_bfloat16*)pwq, (const __nv_bfloat16*)pwk,
        (const __nv_bfloat16*)pwv,
        (float*)pq, (float*)pk, (float*)pv,
        ROWS, DMODEL, KSPLIT);

    int rope_pairs = BATCH * SEQ * HEADS * (DH / 2);
    rope_kernel<<<rope_pairs / 256, 256>>>((float*)pq, qr, 0.08838834764831845f);
    rope_kernel<<<rope_pairs / 256, 256>>>((float*)pk, kr, 1.0f);

    attn_mma_kernel<<<dim3(SEQ / AQT, BATCH * HEADS), 256, ATT2_SMEM_BYTES>>>(
        (const float*)pq, (const float*)pk, (const float*)pv,
        (__nv_bfloat16*)pab);

    gemm_bf16_kernel<<<dim3(DMODEL / GBN, ROWS / GBM), 256, GEMM_SMEM_BYTES>>>(
        (const __nv_bfloat16*)pab, (const __nv_bfloat16*)pwo, out,
        ROWS, DMODEL, KSPLIT, bo);
}